// round 1
// baseline (speedup 1.0000x reference)
#include <cuda_runtime.h>
#include <math.h>

// ---------------- problem constants ----------------
#define Bsz   256
#define TIN   32
#define TOUT  29
#define VDEC  72
#define Esz   256
#define Hsz   256
#define Gsz   1024
#define Dd    6     // 2 dirs * 3 layers
#define Lly   3

// ---------------- scratch (static device memory; no allocs allowed) --------
__device__ float g_enc_out[TIN * Dd * Bsz * Hsz];   // [Tin, D, B, H]  ~50MB
__device__ float g_h_enc[2 * Dd * Bsz * Hsz];
__device__ float g_c_enc[2 * Dd * Bsz * Hsz];
__device__ float g_h_dec[2 * Dd * Bsz * Hsz];
__device__ float g_c_dec[2 * Dd * Bsz * Hsz];
__device__ float g_mixed[Dd * Bsz * Hsz];
__device__ float g_ctx[Bsz * Hsz];
__device__ float g_xdec[Bsz * Esz];
__device__ float g_loA[Bsz * 2 * Hsz];
__device__ float g_loB[Bsz * 2 * Hsz];

// ---------------- init: zero initial states + initialize output ------------
__global__ void init_kernel(float* __restrict__ out, long nout,
                            float* __restrict__ h0, float* __restrict__ c0) {
    long i = (long)blockIdx.x * blockDim.x + threadIdx.x;
    if (i < (long)Dd * Bsz * Hsz) { h0[i] = 0.f; c0[i] = 0.f; }
    if (i < nout) {
        float v = 0.f;
        if (i < (long)Bsz * VDEC && (i % VDEC) == 1) v = 1.f;  // predicted[0,:,1]=1
        out[i] = v;
    }
}

// ---------------- fused LSTM layer: gate GEMMs + activations + state update -
// g[b,n] = inp[b,:]·Wih[n,:] + h[b,:]·Whh[n,:] + bias[n], n = q*256 + j (q=i,f,g,o)
// grid: (H/32, B/32, 2 dirs), block: 256 threads, each computes 2x2 outputs x4 gates
__global__ __launch_bounds__(256) void lstm_gate_kernel(
    const float* __restrict__ inp,    // [B, Kin] or null -> gather emb
    const int*   __restrict__ tok,    // token ptr (if inp==null), token = tok[b*tok_stride]
    int tok_stride,
    const float* __restrict__ emb,    // [V, 256]
    int Kin,
    const float* __restrict__ Wih,    // dir-0 base, dir stride dWih elements
    long dWih,
    const float* __restrict__ Whh_l,  // [2, G, H] for this layer
    const float* __restrict__ bias_l, // [2, G]
    const float* __restrict__ h_in,   // [6,B,H] parity p
    const float* __restrict__ c_in,
    float* __restrict__ h_out,        // parity 1-p
    float* __restrict__ c_out,
    float* __restrict__ lo_out,       // [B, 2H], columns d*H + j
    int layer)
{
    __shared__ float As[32][33];
    __shared__ float Ws[4][32][33];

    const int d  = blockIdx.z;
    const int jt = blockIdx.x * 32;
    const int bt = blockIdx.y * 32;
    const int idx = 2 * layer + d;

    const float* Wd    = Wih   + (size_t)d * dWih;
    const float* Whd   = Whh_l + (size_t)d * Gsz * Hsz;
    const float* bd    = bias_l + d * Gsz;
    const float* hprev = h_in + (size_t)idx * Bsz * Hsz;
    const float* cprev = c_in + (size_t)idx * Bsz * Hsz;

    const int tid = threadIdx.x;
    const int tx = tid & 15, ty = tid >> 4;

    float acc[4][2][2] = {};

    // ---- phase 1: input contribution ----
    for (int k0 = 0; k0 < Kin; k0 += 32) {
        #pragma unroll
        for (int i = 0; i < 4; i++) {
            int e2 = tid + i * 256;
            int r = e2 >> 5, c = e2 & 31;
            int b_ = bt + r, k = k0 + c;
            float v;
            if (inp) v = inp[(size_t)b_ * Kin + k];
            else     v = emb[(size_t)tok[(size_t)b_ * tok_stride] * Esz + k];
            As[r][c] = v;
        }
        #pragma unroll
        for (int q = 0; q < 4; q++)
            #pragma unroll
            for (int i = 0; i < 4; i++) {
                int e2 = tid + i * 256;
                int r = e2 >> 5, c = e2 & 31;
                Ws[q][r][c] = Wd[(size_t)(q * Hsz + jt + r) * Kin + k0 + c];
            }
        __syncthreads();
        #pragma unroll
        for (int kk = 0; kk < 32; kk++) {
            float a0 = As[ty * 2][kk], a1 = As[ty * 2 + 1][kk];
            #pragma unroll
            for (int q = 0; q < 4; q++) {
                float w0 = Ws[q][tx * 2][kk], w1 = Ws[q][tx * 2 + 1][kk];
                acc[q][0][0] += a0 * w0; acc[q][0][1] += a0 * w1;
                acc[q][1][0] += a1 * w0; acc[q][1][1] += a1 * w1;
            }
        }
        __syncthreads();
    }

    // ---- phase 2: hidden contribution ----
    for (int k0 = 0; k0 < Hsz; k0 += 32) {
        #pragma unroll
        for (int i = 0; i < 4; i++) {
            int e2 = tid + i * 256;
            int r = e2 >> 5, c = e2 & 31;
            As[r][c] = hprev[(size_t)(bt + r) * Hsz + k0 + c];
        }
        #pragma unroll
        for (int q = 0; q < 4; q++)
            #pragma unroll
            for (int i = 0; i < 4; i++) {
                int e2 = tid + i * 256;
                int r = e2 >> 5, c = e2 & 31;
                Ws[q][r][c] = Whd[(size_t)(q * Hsz + jt + r) * Hsz + k0 + c];
            }
        __syncthreads();
        #pragma unroll
        for (int kk = 0; kk < 32; kk++) {
            float a0 = As[ty * 2][kk], a1 = As[ty * 2 + 1][kk];
            #pragma unroll
            for (int q = 0; q < 4; q++) {
                float w0 = Ws[q][tx * 2][kk], w1 = Ws[q][tx * 2 + 1][kk];
                acc[q][0][0] += a0 * w0; acc[q][0][1] += a0 * w1;
                acc[q][1][0] += a1 * w0; acc[q][1][1] += a1 * w1;
            }
        }
        __syncthreads();
    }

    // ---- epilogue: torch gate order i,f,g,o ----
    #pragma unroll
    for (int rb = 0; rb < 2; rb++)
        #pragma unroll
        for (int rj = 0; rj < 2; rj++) {
            int b_ = bt + ty * 2 + rb;
            int j_ = jt + tx * 2 + rj;
            float ig = acc[0][rb][rj] + bd[0 * Hsz + j_];
            float fg = acc[1][rb][rj] + bd[1 * Hsz + j_];
            float gg = acc[2][rb][rj] + bd[2 * Hsz + j_];
            float og = acc[3][rb][rj] + bd[3 * Hsz + j_];
            float si = 1.f / (1.f + expf(-ig));
            float sf = 1.f / (1.f + expf(-fg));
            float so = 1.f / (1.f + expf(-og));
            float tg = tanhf(gg);
            float cold = cprev[(size_t)b_ * Hsz + j_];
            float cn = sf * cold + si * tg;
            float hn = so * tanhf(cn);
            c_out[(size_t)idx * Bsz * Hsz + (size_t)b_ * Hsz + j_] = cn;
            h_out[(size_t)idx * Bsz * Hsz + (size_t)b_ * Hsz + j_] = hn;
            lo_out[(size_t)b_ * (2 * Hsz) + d * Hsz + j_] = hn;
        }
}

// ---------------- proj: mix over D with W2 (6x6), then GEMM with W1 --------
// mixed[m,b,h] = sum_l W2[m,l] * hid[l,b,h]
__global__ void proj_mix_kernel(const float* __restrict__ hid,
                                const float* __restrict__ W2,
                                float* __restrict__ mixed) {
    int i = blockIdx.x * blockDim.x + threadIdx.x;  // b*H + h
    int b = i >> 8, h = i & 255;
    float hv[Dd];
    #pragma unroll
    for (int l = 0; l < Dd; l++) hv[l] = hid[((size_t)l * Bsz + b) * Hsz + h];
    #pragma unroll
    for (int m = 0; m < Dd; m++) {
        float s = 0.f;
        #pragma unroll
        for (int l = 0; l < Dd; l++) s += W2[m * Dd + l] * hv[l];
        mixed[((size_t)m * Bsz + b) * Hsz + h] = s;
    }
}

// out[row, g] = sum_h mixed[row,h]*W1[g,h] + (sum_l W2[m,l])*b1[g] + b2[m], row = m*B+b
// grid: (256/32, 1536/32)
__global__ __launch_bounds__(256) void proj_gemm_kernel(
    const float* __restrict__ Amat,  // [1536, 256]
    const float* __restrict__ W1,    // [256, 256]
    const float* __restrict__ b1,
    const float* __restrict__ W2,    // [6,6]
    const float* __restrict__ b2,    // [6]
    float* __restrict__ outp)        // [1536, 256]
{
    __shared__ float As[32][33];
    __shared__ float Bs[32][33];
    const int gt = blockIdx.x * 32;
    const int rt = blockIdx.y * 32;
    const int tid = threadIdx.x;
    const int tx = tid & 15, ty = tid >> 4;
    float acc[2][2] = {};

    for (int k0 = 0; k0 < 256; k0 += 32) {
        #pragma unroll
        for (int i = 0; i < 4; i++) {
            int e2 = tid + i * 256;
            int r = e2 >> 5, c = e2 & 31;
            As[r][c] = Amat[(size_t)(rt + r) * 256 + k0 + c];
            Bs[r][c] = W1[(size_t)(gt + r) * 256 + k0 + c];
        }
        __syncthreads();
        #pragma unroll
        for (int kk = 0; kk < 32; kk++) {
            float a0 = As[ty * 2][kk], a1 = As[ty * 2 + 1][kk];
            float w0 = Bs[tx * 2][kk], w1 = Bs[tx * 2 + 1][kk];
            acc[0][0] += a0 * w0; acc[0][1] += a0 * w1;
            acc[1][0] += a1 * w0; acc[1][1] += a1 * w1;
        }
        __syncthreads();
    }
    #pragma unroll
    for (int rr = 0; rr < 2; rr++)
        #pragma unroll
        for (int rg = 0; rg < 2; rg++) {
            int row = rt + ty * 2 + rr;
            int g = gt + tx * 2 + rg;
            int m = row >> 8;
            float sw2 = 0.f;
            #pragma unroll
            for (int l = 0; l < Dd; l++) sw2 += W2[m * Dd + l];
            outp[(size_t)row * 256 + g] = acc[rr][rg] + sw2 * b1[g] + b2[m];
        }
}

// ---------------- attention: per (b,j), softmax over Tin for each l, mean over l
__global__ void attn_kernel(const float* __restrict__ hcur,   // [6,B,H]
                            const float* __restrict__ eo,     // [Tin,6,B,H]
                            float* __restrict__ ctx) {
    int i = blockIdx.x * blockDim.x + threadIdx.x;  // b*H + j
    int b = i >> 8, j = i & 255;
    float acc = 0.f;
    #pragma unroll 1
    for (int l = 0; l < Dd; l++) {
        float hv = hcur[((size_t)l * Bsz + b) * Hsz + j];
        float eor[TIN];
        #pragma unroll
        for (int t = 0; t < TIN; t++)
            eor[t] = eo[(((size_t)t * Dd + l) * Bsz + b) * Hsz + j];
        float m = -1e30f;
        #pragma unroll
        for (int t = 0; t < TIN; t++) m = fmaxf(m, hv * eor[t]);
        float s = 0.f, w = 0.f;
        #pragma unroll
        for (int t = 0; t < TIN; t++) {
            float p = expf(hv * eor[t] - m);
            s += p; w += p * eor[t];
        }
        acc += w / s;
    }
    ctx[i] = acc * (1.f / 6.f);
}

// ---------------- attention linear: x = [emb(tok), ctx] @ attn_W^T + attn_b -
__global__ __launch_bounds__(256) void attnlin_kernel(
    const int* __restrict__ tok, int tok_stride,
    const float* __restrict__ dec_emb,   // [Vdec, 256]
    const float* __restrict__ ctx,       // [B, 256]
    const float* __restrict__ W,         // [256, 512]
    const float* __restrict__ bvec,      // [256]
    float* __restrict__ xdec)            // [B, 256]
{
    __shared__ float As[32][33];
    __shared__ float Bs[32][33];
    const int et = blockIdx.x * 32;
    const int bt = blockIdx.y * 32;
    const int tid = threadIdx.x;
    const int tx = tid & 15, ty = tid >> 4;
    float acc[2][2] = {};

    for (int k0 = 0; k0 < 512; k0 += 32) {
        #pragma unroll
        for (int i = 0; i < 4; i++) {
            int e2 = tid + i * 256;
            int r = e2 >> 5, c = e2 & 31;
            int b_ = bt + r, k = k0 + c;
            float v;
            if (k < 256) v = dec_emb[(size_t)tok[(size_t)b_ * tok_stride] * 256 + k];
            else         v = ctx[(size_t)b_ * 256 + (k - 256)];
            As[r][c] = v;
            Bs[r][c] = W[(size_t)(et + r) * 512 + k];
        }
        __syncthreads();
        #pragma unroll
        for (int kk = 0; kk < 32; kk++) {
            float a0 = As[ty * 2][kk], a1 = As[ty * 2 + 1][kk];
            float w0 = Bs[tx * 2][kk], w1 = Bs[tx * 2 + 1][kk];
            acc[0][0] += a0 * w0; acc[0][1] += a0 * w1;
            acc[1][0] += a1 * w0; acc[1][1] += a1 * w1;
        }
        __syncthreads();
    }
    #pragma unroll
    for (int rr = 0; rr < 2; rr++)
        #pragma unroll
        for (int re = 0; re < 2; re++) {
            int b_ = bt + ty * 2 + rr;
            int e = et + tx * 2 + re;
            xdec[(size_t)b_ * 256 + e] = acc[rr][re] + bvec[e];
        }
}

// ---------------- fc: logits[b,v] = top[b,:]·fc_W[v,:] + fc_b[v] ------------
__global__ void fc_kernel(const float* __restrict__ top,   // [B, 512]
                          const float* __restrict__ W,     // [72, 512]
                          const float* __restrict__ bv,
                          float* __restrict__ outp) {      // [B, 72]
    int i = blockIdx.x * blockDim.x + threadIdx.x;
    if (i >= Bsz * VDEC) return;
    int b = i / VDEC, v = i % VDEC;
    float s = bv[v];
    const float* tr = top + (size_t)b * 512;
    const float* wr = W + (size_t)v * 512;
    #pragma unroll 8
    for (int k = 0; k < 512; k++) s += tr[k] * wr[k];
    outp[(size_t)b * VDEC + v] = s;
}

// ============================================================================
extern "C" void kernel_launch(void* const* d_in, const int* in_sizes, int n_in,
                              void* d_out, int out_size) {
    // inputs (metadata order)
    const int*   input    = (const int*)  d_in[0];   // [B, Tin]
    const int*   target   = (const int*)  d_in[1];   // [B, Tout]
    // d_in[2] = teacher_force (==1 in this dataset; teacher-forced path)
    const float* enc_emb  = (const float*)d_in[3];
    const float* dec_emb  = (const float*)d_in[4];
    const float* enc_Wih0 = (const float*)d_in[5];   // [2, G, E]
    const float* enc_Wih1 = (const float*)d_in[6];   // [2, 2, G, 2H]
    const float* enc_Whh  = (const float*)d_in[7];   // [3, 2, G, H]
    const float* enc_b    = (const float*)d_in[8];   // [3, 2, G]
    const float* dec_Wih0 = (const float*)d_in[9];
    const float* dec_Wih1 = (const float*)d_in[10];
    const float* dec_Whh  = (const float*)d_in[11];
    const float* dec_b    = (const float*)d_in[12];
    const float* lin_h_W1 = (const float*)d_in[13];
    const float* lin_h_b1 = (const float*)d_in[14];
    const float* lin_h_W2 = (const float*)d_in[15];
    const float* lin_h_b2 = (const float*)d_in[16];
    const float* lin_c_W1 = (const float*)d_in[17];
    const float* lin_c_b1 = (const float*)d_in[18];
    const float* lin_c_W2 = (const float*)d_in[19];
    const float* lin_c_b2 = (const float*)d_in[20];
    const float* lin_a_W1 = (const float*)d_in[21];
    const float* lin_a_b1 = (const float*)d_in[22];
    const float* lin_a_W2 = (const float*)d_in[23];
    const float* lin_a_b2 = (const float*)d_in[24];
    const float* attn_W   = (const float*)d_in[25];  // [256, 512]
    const float* attn_b   = (const float*)d_in[26];
    const float* fc_W     = (const float*)d_in[27];  // [72, 512]
    const float* fc_b     = (const float*)d_in[28];
    float* out = (float*)d_out;

    // scratch symbol addresses
    float *enc_out, *h_enc, *c_enc, *h_dec, *c_dec, *mixed, *ctx, *xdec, *loA, *loB;
    cudaGetSymbolAddress((void**)&enc_out, g_enc_out);
    cudaGetSymbolAddress((void**)&h_enc,   g_h_enc);
    cudaGetSymbolAddress((void**)&c_enc,   g_c_enc);
    cudaGetSymbolAddress((void**)&h_dec,   g_h_dec);
    cudaGetSymbolAddress((void**)&c_dec,   g_c_dec);
    cudaGetSymbolAddress((void**)&mixed,   g_mixed);
    cudaGetSymbolAddress((void**)&ctx,     g_ctx);
    cudaGetSymbolAddress((void**)&xdec,    g_xdec);
    cudaGetSymbolAddress((void**)&loA,     g_loA);
    cudaGetSymbolAddress((void**)&loB,     g_loB);

    const size_t SLAB = (size_t)Dd * Bsz * Hsz;  // one parity of state

    // init
    {
        long nmax = out_size;
        if ((long)SLAB > nmax) nmax = (long)SLAB;
        int blocks = (int)((nmax + 255) / 256);
        init_kernel<<<blocks, 256>>>(out, (long)out_size, h_enc, c_enc);
    }

    dim3 ggrid(Hsz / 32, Bsz / 32, 2);   // (8, 8, 2)
    dim3 pgrid(256 / 32, (Dd * Bsz) / 32);  // (8, 48)
    dim3 agrid(8, 8);

    // ---------------- encoder ----------------
    for (int t = 0; t < TIN; t++) {
        int p = t & 1;
        const float* hI = h_enc + (size_t)p * SLAB;
        const float* cI = c_enc + (size_t)p * SLAB;
        float* hO = h_enc + (size_t)(1 - p) * SLAB;
        float* cO = c_enc + (size_t)(1 - p) * SLAB;

        // layer 0: gather enc_emb[input[:,t]]
        lstm_gate_kernel<<<ggrid, 256>>>(
            nullptr, input + t, TIN, enc_emb, Esz,
            enc_Wih0, (long)Gsz * Esz,
            enc_Whh + 0, enc_b + 0,
            hI, cI, hO, cO, loA, 0);
        // layer 1
        lstm_gate_kernel<<<ggrid, 256>>>(
            loA, nullptr, 0, nullptr, 2 * Hsz,
            enc_Wih1 + 0, (long)Gsz * 2 * Hsz,
            enc_Whh + (size_t)1 * 2 * Gsz * Hsz, enc_b + 1 * 2 * Gsz,
            hI, cI, hO, cO, loB, 1);
        // layer 2
        lstm_gate_kernel<<<ggrid, 256>>>(
            loB, nullptr, 0, nullptr, 2 * Hsz,
            enc_Wih1 + (size_t)1 * 2 * Gsz * 2 * Hsz, (long)Gsz * 2 * Hsz,
            enc_Whh + (size_t)2 * 2 * Gsz * Hsz, enc_b + 2 * 2 * Gsz,
            hI, cI, hO, cO, loA, 2);

        // attention projection of updated h
        proj_mix_kernel<<<256, 256>>>(hO, lin_a_W2, mixed);
        proj_gemm_kernel<<<pgrid, 256>>>(mixed, lin_a_W1, lin_a_b1, lin_a_W2, lin_a_b2,
                                         enc_out + (size_t)t * SLAB);
    }

    // final encoder states are at parity 0 (t=31 wrote parity 0)
    const float* hF = h_enc + 0 * SLAB;
    const float* cF = c_enc + 0 * SLAB;

    // ---------------- bridging ----------------
    proj_mix_kernel<<<256, 256>>>(hF, lin_h_W2, mixed);
    proj_gemm_kernel<<<pgrid, 256>>>(mixed, lin_h_W1, lin_h_b1, lin_h_W2, lin_h_b2,
                                     h_dec + 0 * SLAB);
    proj_mix_kernel<<<256, 256>>>(cF, lin_c_W2, mixed);
    proj_gemm_kernel<<<pgrid, 256>>>(mixed, lin_c_W1, lin_c_b1, lin_c_W2, lin_c_b2,
                                     c_dec + 0 * SLAB);

    // ---------------- decoder (teacher-forced) ----------------
    for (int s = 0; s < TOUT - 1; s++) {
        int p = s & 1;
        const float* hI = h_dec + (size_t)p * SLAB;
        const float* cI = c_dec + (size_t)p * SLAB;
        float* hO = h_dec + (size_t)(1 - p) * SLAB;
        float* cO = c_dec + (size_t)(1 - p) * SLAB;

        attn_kernel<<<(Bsz * Hsz) / 256, 256>>>(hI, enc_out, ctx);
        attnlin_kernel<<<agrid, 256>>>(target + s, TOUT, dec_emb, ctx,
                                       attn_W, attn_b, xdec);

        lstm_gate_kernel<<<ggrid, 256>>>(
            xdec, nullptr, 0, nullptr, Esz,
            dec_Wih0, (long)Gsz * Esz,
            dec_Whh + 0, dec_b + 0,
            hI, cI, hO, cO, loA, 0);
        lstm_gate_kernel<<<ggrid, 256>>>(
            loA, nullptr, 0, nullptr, 2 * Hsz,
            dec_Wih1 + 0, (long)Gsz * 2 * Hsz,
            dec_Whh + (size_t)1 * 2 * Gsz * Hsz, dec_b + 1 * 2 * Gsz,
            hI, cI, hO, cO, loB, 1);
        lstm_gate_kernel<<<ggrid, 256>>>(
            loB, nullptr, 0, nullptr, 2 * Hsz,
            dec_Wih1 + (size_t)1 * 2 * Gsz * 2 * Hsz, (long)Gsz * 2 * Hsz,
            dec_Whh + (size_t)2 * 2 * Gsz * Hsz, dec_b + 2 * 2 * Gsz,
            hI, cI, hO, cO, loA, 2);

        fc_kernel<<<(Bsz * VDEC + 255) / 256, 256>>>(
            loA, fc_W, fc_b, out + (size_t)(s + 1) * Bsz * VDEC);
    }
}

// round 3
// speedup vs baseline: 1.4776x; 1.4776x over previous
#include <cuda_runtime.h>
#include <math.h>
#include <stdint.h>

// ---------------- problem constants ----------------
#define Bsz   256
#define TIN   32
#define TOUT  29
#define VDEC  72
#define Esz   256
#define Hsz   256
#define Gsz   1024
#define Dd    6     // 2 dirs * 3 layers
#define Lly   3

// ---------------- scratch (static device memory; no allocs allowed) --------
__device__ float g_enc_out[TIN * Dd * Bsz * Hsz];   // [Tin, D, B, H]  ~50MB
__device__ float g_h_enc[2 * Dd * Bsz * Hsz];
__device__ float g_c_enc[2 * Dd * Bsz * Hsz];
__device__ float g_h_dec[2 * Dd * Bsz * Hsz];
__device__ float g_c_dec[2 * Dd * Bsz * Hsz];
__device__ float g_mixed[Dd * Bsz * Hsz];
__device__ float g_ctx[Bsz * Hsz];
__device__ float g_xdec[Bsz * Esz];
__device__ float g_loA[Bsz * 2 * Hsz];
__device__ float g_loB[Bsz * 2 * Hsz];

// ---------------- tf32 helpers ----------------
__device__ __forceinline__ uint32_t f2tf32(float f) {
    uint32_t r;
    asm("cvt.rna.tf32.f32 %0, %1;" : "=r"(r) : "f"(f));
    return r;
}

__device__ __forceinline__ void mma_tf32(float* c,
    uint32_t a0, uint32_t a1, uint32_t a2, uint32_t a3,
    uint32_t b0, uint32_t b1) {
    asm volatile(
        "mma.sync.aligned.m16n8k8.row.col.f32.tf32.tf32.f32 "
        "{%0,%1,%2,%3}, {%4,%5,%6,%7}, {%8,%9}, {%0,%1,%2,%3};"
        : "+f"(c[0]), "+f"(c[1]), "+f"(c[2]), "+f"(c[3])
        : "r"(a0), "r"(a1), "r"(a2), "r"(a3), "r"(b0), "r"(b1));
}

// ---------------- init: zero initial states + initialize output ------------
__global__ void init_kernel(float* __restrict__ out, long nout,
                            float* __restrict__ h0, float* __restrict__ c0) {
    long i = (long)blockIdx.x * blockDim.x + threadIdx.x;
    if (i < (long)Dd * Bsz * Hsz) { h0[i] = 0.f; c0[i] = 0.f; }
    if (i < nout) {
        float v = 0.f;
        if (i < (long)Bsz * VDEC && (i % VDEC) == 1) v = 1.f;  // predicted[0,:,1]=1
        out[i] = v;
    }
}

// ---------------- fused LSTM layer (tf32 tensor-core MMA) -------------------
// g[b,n] = inp[b,:]·Wih[n,:] + h[b,:]·Whh[n,:] + bias[n], n = q*256 + j
// Block tile: 32 b x 32 j x 4 gates. 8 warps: wm=b-half(16), wn=j-group(8).
// Each warp: per k-chunk(8), 1 A-frag + 4 B-frags (one per gate) -> 4 MMA.
// Epilogue: each thread holds all 4 gates for its 4 (b,j) positions.
__global__ __launch_bounds__(256) void lstm_gate_mma(
    const float* __restrict__ inp,    // [B, Kin] or null -> gather emb
    const int*   __restrict__ tok,    // token ptr (if inp==null)
    int tok_stride,
    const float* __restrict__ emb,    // [V, 256]
    int Kin,
    const float* __restrict__ Wih,    // dir-0 base, dir stride dWih
    long dWih,
    const float* __restrict__ Whh_l,  // [2, G, H] for this layer
    const float* __restrict__ bias_l, // [2, G]
    const float* __restrict__ h_in,   // [6,B,H] parity p
    const float* __restrict__ c_in,
    float* __restrict__ h_out,        // parity 1-p
    float* __restrict__ c_out,
    float* __restrict__ lo_out,       // [B, 2H]
    int layer)
{
    __shared__ uint32_t As[32][36];
    __shared__ uint32_t Ws[4][32][36];

    const int d  = blockIdx.z;
    const int jt = blockIdx.x * 32;
    const int bt = blockIdx.y * 32;
    const int idx = 2 * layer + d;

    const float* Wd    = Wih   + (size_t)d * dWih;
    const float* Whd   = Whh_l + (size_t)d * Gsz * Hsz;
    const float* bd    = bias_l + d * Gsz;
    const float* hprev = h_in + (size_t)idx * Bsz * Hsz;
    const float* cprev = c_in + (size_t)idx * Bsz * Hsz;

    const int tid  = threadIdx.x;
    const int warp = tid >> 5, lane = tid & 31;
    const int wm = warp & 1;      // b half (16 rows)
    const int wn = warp >> 1;     // j group (8 cols)
    const int gq = lane >> 2, t4 = lane & 3;

    // staging indices: A tile = 32x32 floats -> 1 float4/thread
    const int ar = tid >> 3;
    const int ac = (tid & 7) * 4;

    float acc[4][4];
    #pragma unroll
    for (int q = 0; q < 4; q++)
        #pragma unroll
        for (int i = 0; i < 4; i++) acc[q][i] = 0.f;

    #pragma unroll 1
    for (int ph = 0; ph < 2; ph++) {
        const float* Asrc = ph ? hprev : inp;
        const int    lda  = ph ? Hsz : Kin;
        const float* Wsrc = ph ? Whd : Wd;
        const int    ldw  = ph ? Hsz : Kin;
        const int    Klen = ph ? Hsz : Kin;
        const bool gather = (ph == 0) && (inp == nullptr);

        for (int k0 = 0; k0 < Klen; k0 += 32) {
            // ---- stage A tile ----
            {
                int b_ = bt + ar;
                const float* src;
                if (gather)
                    src = emb + (size_t)tok[(size_t)b_ * tok_stride] * Esz + k0 + ac;
                else
                    src = Asrc + (size_t)b_ * lda + k0 + ac;
                float4 v = *(const float4*)src;
                As[ar][ac + 0] = f2tf32(v.x);
                As[ar][ac + 1] = f2tf32(v.y);
                As[ar][ac + 2] = f2tf32(v.z);
                As[ar][ac + 3] = f2tf32(v.w);
            }
            // ---- stage W tile: 4 gates x 32 rows x 32 k -> 4 float4/thread ----
            #pragma unroll
            for (int i = 0; i < 4; i++) {
                int e  = tid + i * 256;
                int q  = e >> 8;
                int r  = (e >> 3) & 31;
                int c4 = (e & 7) * 4;
                const float* src = Wsrc + (size_t)(q * Hsz + jt + r) * ldw + k0 + c4;
                float4 v = *(const float4*)src;
                Ws[q][r][c4 + 0] = f2tf32(v.x);
                Ws[q][r][c4 + 1] = f2tf32(v.y);
                Ws[q][r][c4 + 2] = f2tf32(v.z);
                Ws[q][r][c4 + 3] = f2tf32(v.w);
            }
            __syncthreads();

            #pragma unroll
            for (int kc = 0; kc < 32; kc += 8) {
                uint32_t a0 = As[wm * 16 + gq][kc + t4];
                uint32_t a1 = As[wm * 16 + 8 + gq][kc + t4];
                uint32_t a2 = As[wm * 16 + gq][kc + t4 + 4];
                uint32_t a3 = As[wm * 16 + 8 + gq][kc + t4 + 4];
                #pragma unroll
                for (int q = 0; q < 4; q++) {
                    uint32_t b0 = Ws[q][wn * 8 + gq][kc + t4];
                    uint32_t b1 = Ws[q][wn * 8 + gq][kc + t4 + 4];
                    mma_tf32(acc[q], a0, a1, a2, a3, b0, b1);
                }
            }
            __syncthreads();
        }
    }

    // ---- epilogue: torch gate order i,f,g,o; all 4 gates per thread ----
    const int b0r = bt + wm * 16 + gq;
    const int j0  = jt + wn * 8 + t4 * 2;
    #pragma unroll
    for (int rb = 0; rb < 2; rb++)
        #pragma unroll
        for (int rj = 0; rj < 2; rj++) {
            int b_ = b0r + rb * 8;
            int j_ = j0 + rj;
            int ci = rb * 2 + rj;
            float ig = acc[0][ci] + bd[0 * Hsz + j_];
            float fg = acc[1][ci] + bd[1 * Hsz + j_];
            float gg = acc[2][ci] + bd[2 * Hsz + j_];
            float og = acc[3][ci] + bd[3 * Hsz + j_];
            float si = 1.f / (1.f + expf(-ig));
            float sf = 1.f / (1.f + expf(-fg));
            float so = 1.f / (1.f + expf(-og));
            float tg = tanhf(gg);
            float cold = cprev[(size_t)b_ * Hsz + j_];
            float cn = sf * cold + si * tg;
            float hn = so * tanhf(cn);
            c_out[(size_t)idx * Bsz * Hsz + (size_t)b_ * Hsz + j_] = cn;
            h_out[(size_t)idx * Bsz * Hsz + (size_t)b_ * Hsz + j_] = hn;
            lo_out[(size_t)b_ * (2 * Hsz) + d * Hsz + j_] = hn;
        }
}

// ---------------- proj: mix over D with W2 (6x6), then GEMM with W1 --------
__global__ void proj_mix_kernel(const float* __restrict__ hid,
                                const float* __restrict__ W2,
                                float* __restrict__ mixed) {
    int i = blockIdx.x * blockDim.x + threadIdx.x;  // b*H + h
    int b = i >> 8, h = i & 255;
    float hv[Dd];
    #pragma unroll
    for (int l = 0; l < Dd; l++) hv[l] = hid[((size_t)l * Bsz + b) * Hsz + h];
    #pragma unroll
    for (int m = 0; m < Dd; m++) {
        float s = 0.f;
        #pragma unroll
        for (int l = 0; l < Dd; l++) s += W2[m * Dd + l] * hv[l];
        mixed[((size_t)m * Bsz + b) * Hsz + h] = s;
    }
}

// out[row, g] = sum_h mixed[row,h]*W1[g,h] + (sum_l W2[m,l])*b1[g] + b2[m]
// tf32 MMA version. Block: 32 rows x 32 g. grid (8, 48).
__global__ __launch_bounds__(256) void proj_gemm_mma(
    const float* __restrict__ Amat,  // [1536, 256]
    const float* __restrict__ W1,    // [256, 256]
    const float* __restrict__ b1,
    const float* __restrict__ W2,    // [6,6]
    const float* __restrict__ b2,    // [6]
    float* __restrict__ outp)        // [1536, 256]
{
    __shared__ uint32_t As[32][36];
    __shared__ uint32_t Bs[32][36];
    const int gt = blockIdx.x * 32;
    const int rt = blockIdx.y * 32;
    const int tid  = threadIdx.x;
    const int warp = tid >> 5, lane = tid & 31;
    const int wm = warp & 1, wn = warp >> 1;
    const int gq = lane >> 2, t4 = lane & 3;
    const int ar = tid >> 3;
    const int ac = (tid & 7) * 4;

    float acc[4] = {0.f, 0.f, 0.f, 0.f};

    for (int k0 = 0; k0 < 256; k0 += 32) {
        {
            float4 va = *(const float4*)(Amat + (size_t)(rt + ar) * 256 + k0 + ac);
            As[ar][ac + 0] = f2tf32(va.x); As[ar][ac + 1] = f2tf32(va.y);
            As[ar][ac + 2] = f2tf32(va.z); As[ar][ac + 3] = f2tf32(va.w);
            float4 vb = *(const float4*)(W1 + (size_t)(gt + ar) * 256 + k0 + ac);
            Bs[ar][ac + 0] = f2tf32(vb.x); Bs[ar][ac + 1] = f2tf32(vb.y);
            Bs[ar][ac + 2] = f2tf32(vb.z); Bs[ar][ac + 3] = f2tf32(vb.w);
        }
        __syncthreads();
        #pragma unroll
        for (int kc = 0; kc < 32; kc += 8) {
            uint32_t a0 = As[wm * 16 + gq][kc + t4];
            uint32_t a1 = As[wm * 16 + 8 + gq][kc + t4];
            uint32_t a2 = As[wm * 16 + gq][kc + t4 + 4];
            uint32_t a3 = As[wm * 16 + 8 + gq][kc + t4 + 4];
            uint32_t b0 = Bs[wn * 8 + gq][kc + t4];
            uint32_t b1r = Bs[wn * 8 + gq][kc + t4 + 4];
            mma_tf32(acc, a0, a1, a2, a3, b0, b1r);
        }
        __syncthreads();
    }

    const int r0 = rt + wm * 16 + gq;
    const int g0 = gt + wn * 8 + t4 * 2;
    #pragma unroll
    for (int rb = 0; rb < 2; rb++)
        #pragma unroll
        for (int rg = 0; rg < 2; rg++) {
            int row = r0 + rb * 8;
            int g = g0 + rg;
            int m = row >> 8;
            float sw2 = 0.f;
            #pragma unroll
            for (int l = 0; l < Dd; l++) sw2 += W2[m * Dd + l];
            outp[(size_t)row * 256 + g] = acc[rb * 2 + rg] + sw2 * b1[g] + b2[m];
        }
}

// ---------------- attention: per (b,j), softmax over Tin per l, mean over l
__global__ void attn_kernel(const float* __restrict__ hcur,   // [6,B,H]
                            const float* __restrict__ eo,     // [Tin,6,B,H]
                            float* __restrict__ ctx) {
    int i = blockIdx.x * blockDim.x + threadIdx.x;  // b*H + j
    int b = i >> 8, j = i & 255;
    float acc = 0.f;
    #pragma unroll 1
    for (int l = 0; l < Dd; l++) {
        float hv = hcur[((size_t)l * Bsz + b) * Hsz + j];
        float eor[TIN];
        #pragma unroll
        for (int t = 0; t < TIN; t++)
            eor[t] = eo[(((size_t)t * Dd + l) * Bsz + b) * Hsz + j];
        float m = -1e30f;
        #pragma unroll
        for (int t = 0; t < TIN; t++) m = fmaxf(m, hv * eor[t]);
        float s = 0.f, w = 0.f;
        #pragma unroll
        for (int t = 0; t < TIN; t++) {
            float p = expf(hv * eor[t] - m);
            s += p; w += p * eor[t];
        }
        acc += w / s;
    }
    ctx[i] = acc * (1.f / 6.f);
}

// ---------------- attention linear: x = [emb(tok), ctx] @ attn_W^T + attn_b -
__global__ __launch_bounds__(256) void attnlin_kernel(
    const int* __restrict__ tok, int tok_stride,
    const float* __restrict__ dec_emb,   // [Vdec, 256]
    const float* __restrict__ ctx,       // [B, 256]
    const float* __restrict__ W,         // [256, 512]
    const float* __restrict__ bvec,      // [256]
    float* __restrict__ xdec)            // [B, 256]
{
    __shared__ float As[32][33];
    __shared__ float Bs[32][33];
    const int et = blockIdx.x * 32;
    const int bt = blockIdx.y * 32;
    const int tid = threadIdx.x;
    const int tx = tid & 15, ty = tid >> 4;
    float acc[2][2] = {};

    for (int k0 = 0; k0 < 512; k0 += 32) {
        #pragma unroll
        for (int i = 0; i < 4; i++) {
            int e2 = tid + i * 256;
            int r = e2 >> 5, c = e2 & 31;
            int b_ = bt + r, k = k0 + c;
            float v;
            if (k < 256) v = dec_emb[(size_t)tok[(size_t)b_ * tok_stride] * 256 + k];
            else         v = ctx[(size_t)b_ * 256 + (k - 256)];
            As[r][c] = v;
            Bs[r][c] = W[(size_t)(et + r) * 512 + k];
        }
        __syncthreads();
        #pragma unroll
        for (int kk = 0; kk < 32; kk++) {
            float a0 = As[ty * 2][kk], a1 = As[ty * 2 + 1][kk];
            float w0 = Bs[tx * 2][kk], w1 = Bs[tx * 2 + 1][kk];
            acc[0][0] += a0 * w0; acc[0][1] += a0 * w1;
            acc[1][0] += a1 * w0; acc[1][1] += a1 * w1;
        }
        __syncthreads();
    }
    #pragma unroll
    for (int rr = 0; rr < 2; rr++)
        #pragma unroll
        for (int re = 0; re < 2; re++) {
            int b_ = bt + ty * 2 + rr;
            int e = et + tx * 2 + re;
            xdec[(size_t)b_ * 256 + e] = acc[rr][re] + bvec[e];
        }
}

// ---------------- fc: logits[b,v] = top[b,:]·fc_W[v,:] + fc_b[v] ------------
__global__ void fc_kernel(const float* __restrict__ top,   // [B, 512]
                          const float* __restrict__ W,     // [72, 512]
                          const float* __restrict__ bv,
                          float* __restrict__ outp) {      // [B, 72]
    int i = blockIdx.x * blockDim.x + threadIdx.x;
    if (i >= Bsz * VDEC) return;
    int b = i / VDEC, v = i % VDEC;
    float s = bv[v];
    const float* tr = top + (size_t)b * 512;
    const float* wr = W + (size_t)v * 512;
    #pragma unroll 8
    for (int k = 0; k < 512; k++) s += tr[k] * wr[k];
    outp[(size_t)b * VDEC + v] = s;
}

// ============================================================================
extern "C" void kernel_launch(void* const* d_in, const int* in_sizes, int n_in,
                              void* d_out, int out_size) {
    const int*   input    = (const int*)  d_in[0];   // [B, Tin]
    const int*   target   = (const int*)  d_in[1];   // [B, Tout]
    const float* enc_emb  = (const float*)d_in[3];
    const float* dec_emb  = (const float*)d_in[4];
    const float* enc_Wih0 = (const float*)d_in[5];   // [2, G, E]
    const float* enc_Wih1 = (const float*)d_in[6];   // [2, 2, G, 2H]
    const float* enc_Whh  = (const float*)d_in[7];   // [3, 2, G, H]
    const float* enc_b    = (const float*)d_in[8];   // [3, 2, G]
    const float* dec_Wih0 = (const float*)d_in[9];
    const float* dec_Wih1 = (const float*)d_in[10];
    const float* dec_Whh  = (const float*)d_in[11];
    const float* dec_b    = (const float*)d_in[12];
    const float* lin_h_W1 = (const float*)d_in[13];
    const float* lin_h_b1 = (const float*)d_in[14];
    const float* lin_h_W2 = (const float*)d_in[15];
    const float* lin_h_b2 = (const float*)d_in[16];
    const float* lin_c_W1 = (const float*)d_in[17];
    const float* lin_c_b1 = (const float*)d_in[18];
    const float* lin_c_W2 = (const float*)d_in[19];
    const float* lin_c_b2 = (const float*)d_in[20];
    const float* lin_a_W1 = (const float*)d_in[21];
    const float* lin_a_b1 = (const float*)d_in[22];
    const float* lin_a_W2 = (const float*)d_in[23];
    const float* lin_a_b2 = (const float*)d_in[24];
    const float* attn_W   = (const float*)d_in[25];  // [256, 512]
    const float* attn_b   = (const float*)d_in[26];
    const float* fc_W     = (const float*)d_in[27];  // [72, 512]
    const float* fc_b     = (const float*)d_in[28];
    float* out = (float*)d_out;

    float *enc_out, *h_enc, *c_enc, *h_dec, *c_dec, *mixed, *ctx, *xdec, *loA, *loB;
    cudaGetSymbolAddress((void**)&enc_out, g_enc_out);
    cudaGetSymbolAddress((void**)&h_enc,   g_h_enc);
    cudaGetSymbolAddress((void**)&c_enc,   g_c_enc);
    cudaGetSymbolAddress((void**)&h_dec,   g_h_dec);
    cudaGetSymbolAddress((void**)&c_dec,   g_c_dec);
    cudaGetSymbolAddress((void**)&mixed,   g_mixed);
    cudaGetSymbolAddress((void**)&ctx,     g_ctx);
    cudaGetSymbolAddress((void**)&xdec,    g_xdec);
    cudaGetSymbolAddress((void**)&loA,     g_loA);
    cudaGetSymbolAddress((void**)&loB,     g_loB);

    const size_t SLAB = (size_t)Dd * Bsz * Hsz;  // one parity of state

    {
        long nmax = out_size;
        if ((long)SLAB > nmax) nmax = (long)SLAB;
        int blocks = (int)((nmax + 255) / 256);
        init_kernel<<<blocks, 256>>>(out, (long)out_size, h_enc, c_enc);
    }

    dim3 ggrid(Hsz / 32, Bsz / 32, 2);       // (8, 8, 2)
    dim3 pgrid(256 / 32, (Dd * Bsz) / 32);   // (8, 48)
    dim3 agrid(8, 8);

    // ---------------- encoder ----------------
    for (int t = 0; t < TIN; t++) {
        int p = t & 1;
        const float* hI = h_enc + (size_t)p * SLAB;
        const float* cI = c_enc + (size_t)p * SLAB;
        float* hO = h_enc + (size_t)(1 - p) * SLAB;
        float* cO = c_enc + (size_t)(1 - p) * SLAB;

        lstm_gate_mma<<<ggrid, 256>>>(
            nullptr, input + t, TIN, enc_emb, Esz,
            enc_Wih0, (long)Gsz * Esz,
            enc_Whh + 0, enc_b + 0,
            hI, cI, hO, cO, loA, 0);
        lstm_gate_mma<<<ggrid, 256>>>(
            loA, nullptr, 0, nullptr, 2 * Hsz,
            enc_Wih1 + 0, (long)Gsz * 2 * Hsz,
            enc_Whh + (size_t)1 * 2 * Gsz * Hsz, enc_b + 1 * 2 * Gsz,
            hI, cI, hO, cO, loB, 1);
        lstm_gate_mma<<<ggrid, 256>>>(
            loB, nullptr, 0, nullptr, 2 * Hsz,
            enc_Wih1 + (size_t)1 * 2 * Gsz * 2 * Hsz, (long)Gsz * 2 * Hsz,
            enc_Whh + (size_t)2 * 2 * Gsz * Hsz, enc_b + 2 * 2 * Gsz,
            hI, cI, hO, cO, loA, 2);

        proj_mix_kernel<<<256, 256>>>(hO, lin_a_W2, mixed);
        proj_gemm_mma<<<pgrid, 256>>>(mixed, lin_a_W1, lin_a_b1, lin_a_W2, lin_a_b2,
                                      enc_out + (size_t)t * SLAB);
    }

    const float* hF = h_enc + 0 * SLAB;
    const float* cF = c_enc + 0 * SLAB;

    // ---------------- bridging ----------------
    proj_mix_kernel<<<256, 256>>>(hF, lin_h_W2, mixed);
    proj_gemm_mma<<<pgrid, 256>>>(mixed, lin_h_W1, lin_h_b1, lin_h_W2, lin_h_b2,
                                  h_dec + 0 * SLAB);
    proj_mix_kernel<<<256, 256>>>(cF, lin_c_W2, mixed);
    proj_gemm_mma<<<pgrid, 256>>>(mixed, lin_c_W1, lin_c_b1, lin_c_W2, lin_c_b2,
                                  c_dec + 0 * SLAB);

    // ---------------- decoder (teacher-forced) ----------------
    for (int s = 0; s < TOUT - 1; s++) {
        int p = s & 1;
        const float* hI = h_dec + (size_t)p * SLAB;
        const float* cI = c_dec + (size_t)p * SLAB;
        float* hO = h_dec + (size_t)(1 - p) * SLAB;
        float* cO = c_dec + (size_t)(1 - p) * SLAB;

        attn_kernel<<<(Bsz * Hsz) / 256, 256>>>(hI, enc_out, ctx);
        attnlin_kernel<<<agrid, 256>>>(target + s, TOUT, dec_emb, ctx,
                                       attn_W, attn_b, xdec);

        lstm_gate_mma<<<ggrid, 256>>>(
            xdec, nullptr, 0, nullptr, Esz,
            dec_Wih0, (long)Gsz * Esz,
            dec_Whh + 0, dec_b + 0,
            hI, cI, hO, cO, loA, 0);
        lstm_gate_mma<<<ggrid, 256>>>(
            loA, nullptr, 0, nullptr, 2 * Hsz,
            dec_Wih1 + 0, (long)Gsz * 2 * Hsz,
            dec_Whh + (size_t)1 * 2 * Gsz * Hsz, dec_b + 1 * 2 * Gsz,
            hI, cI, hO, cO, loB, 1);
        lstm_gate_mma<<<ggrid, 256>>>(
            loB, nullptr, 0, nullptr, 2 * Hsz,
            dec_Wih1 + (size_t)1 * 2 * Gsz * 2 * Hsz, (long)Gsz * 2 * Hsz,
            dec_Whh + (size_t)2 * 2 * Gsz * Hsz, dec_b + 2 * 2 * Gsz,
            hI, cI, hO, cO, loA, 2);

        fc_kernel<<<(Bsz * VDEC + 255) / 256, 256>>>(
            loA, fc_W, fc_b, out + (size_t)(s + 1) * Bsz * VDEC);
    }
}

// round 4
// speedup vs baseline: 1.8212x; 1.2326x over previous
#include <cuda_runtime.h>
#include <math.h>
#include <stdint.h>

// ---------------- problem constants ----------------
#define Bsz   256
#define TIN   32
#define TOUT  29
#define VDEC  72
#define Esz   256
#define Hsz   256
#define Gsz   1024
#define Dd    6
#define Lly   3

// ---------------- scratch ----------------
__device__ float g_enc_out[TIN * Dd * Bsz * Hsz];   // ~50MB
__device__ float g_h_enc[2 * Dd * Bsz * Hsz];
__device__ float g_c_enc[2 * Dd * Bsz * Hsz];
__device__ float g_h_dec[2 * Dd * Bsz * Hsz];
__device__ float g_c_dec[2 * Dd * Bsz * Hsz];
__device__ float g_ctx[Bsz * Hsz];
__device__ float g_xdec[Bsz * Esz];
__device__ float g_loA[Bsz * 2 * Hsz];
__device__ float g_loB[Bsz * 2 * Hsz];
// pre-converted tf32 gate weights, per net: [l0: 2*1024*512][l1: 2*1024*768][l2: 2*1024*768]
#define WNET 4194304
__device__ uint32_t g_wcat[2 * WNET];               // 32MB

// ---------------- helpers ----------------
__device__ __forceinline__ uint32_t f2tf32(float f) {
    uint32_t r;
    asm("cvt.rna.tf32.f32 %0, %1;" : "=r"(r) : "f"(f));
    return r;
}
__device__ __forceinline__ void mma_tf32(float* c,
    uint32_t a0, uint32_t a1, uint32_t a2, uint32_t a3,
    uint32_t b0, uint32_t b1) {
    asm volatile(
        "mma.sync.aligned.m16n8k8.row.col.f32.tf32.tf32.f32 "
        "{%0,%1,%2,%3}, {%4,%5,%6,%7}, {%8,%9}, {%0,%1,%2,%3};"
        : "+f"(c[0]), "+f"(c[1]), "+f"(c[2]), "+f"(c[3])
        : "r"(a0), "r"(a1), "r"(a2), "r"(a3), "r"(b0), "r"(b1));
}
__device__ __forceinline__ void cp_async16(uint32_t dst_smem, const void* src) {
    asm volatile("cp.async.ca.shared.global [%0], [%1], 16;" :: "r"(dst_smem), "l"(src));
}
__device__ __forceinline__ void cp_commit() { asm volatile("cp.async.commit_group;"); }
template<int N> __device__ __forceinline__ void cp_wait() {
    asm volatile("cp.async.wait_group %0;" :: "n"(N));
}

// ---------------- init ----------------
__global__ void init_kernel(float* __restrict__ out, long nout,
                            float* __restrict__ h0, float* __restrict__ c0) {
    long i = (long)blockIdx.x * blockDim.x + threadIdx.x;
    if (i < (long)Dd * Bsz * Hsz) { h0[i] = 0.f; c0[i] = 0.f; }
    if (i < nout) {
        float v = 0.f;
        if (i < (long)Bsz * VDEC && (i % VDEC) == 1) v = 1.f;
        out[i] = v;
    }
}

// ---------------- weight prep: fp32 -> tf32, concatenated [Wih|Whh] layout --
// per net layout (u32 units): l0 @0 (2*1024*512), l1 @1048576, l2 @2621440 (each 2*1024*768)
__global__ void prep_weights(const float* __restrict__ eW0, const float* __restrict__ eW1,
                             const float* __restrict__ eWhh,
                             const float* __restrict__ dW0, const float* __restrict__ dW1,
                             const float* __restrict__ dWhh,
                             uint32_t* __restrict__ wcat) {
    long idx = (long)blockIdx.x * blockDim.x + threadIdx.x;   // 4-element units
    if (idx >= 2 * (WNET / 4)) return;
    int n = (int)(idx >= (WNET / 4));
    long r0 = idx - (long)n * (WNET / 4);
    int l, Kcat4, Kin; long base4;
    if (r0 < 262144)        { l = 0; base4 = 0;      Kcat4 = 128; Kin = 256; }
    else if (r0 < 655360)   { l = 1; base4 = 262144; Kcat4 = 192; Kin = 512; }
    else                    { l = 2; base4 = 655360; Kcat4 = 192; Kin = 512; }
    long r1 = r0 - base4;
    int d  = (int)(r1 / (1024L * Kcat4));
    int rr = (int)((r1 / Kcat4) & 1023);
    int k  = (int)(r1 % Kcat4) * 4;

    const float* W0  = n ? dW0  : eW0;
    const float* W1  = n ? dW1  : eW1;
    const float* Whh = n ? dWhh : eWhh;
    float4 v;
    if (k < Kin) {
        if (l == 0) v = *(const float4*)(W0 + ((size_t)d * 1024 + rr) * 256 + k);
        else        v = *(const float4*)(W1 + (((size_t)(l - 1) * 2 + d) * 1024 + rr) * 512 + k);
    } else {
        v = *(const float4*)(Whh + (((size_t)l * 2 + d) * 1024 + rr) * 256 + (k - Kin));
    }
    uint4 o = make_uint4(f2tf32(v.x), f2tf32(v.y), f2tf32(v.z), f2tf32(v.w));
    *(uint4*)(wcat + idx * 4) = o;
}

// ---------------- fused LSTM layer: single-GEMM, cp.async double-buffered ---
// Block tile: 32 b x 32 j x 4 gates; grid (8,8,2dirs); 256 threads.
__global__ __launch_bounds__(256) void lstm_gate_mma3(
    const float* __restrict__ inp,    // [B, Kin] or null -> gather emb
    const int*   __restrict__ tok, int tok_stride,
    const float* __restrict__ emb,
    int Kin, int Kcat,
    const uint32_t* __restrict__ Wcat, long dW,   // dir stride in u32
    const float* __restrict__ bias_l,             // [2, G]
    const float* __restrict__ h_in, const float* __restrict__ c_in,
    float* __restrict__ h_out, float* __restrict__ c_out,
    float* __restrict__ lo_out, int layer)
{
    __shared__ uint32_t As[2][32][36];
    __shared__ uint32_t Ws[2][4][32][36];

    const int d  = blockIdx.z;
    const int jt = blockIdx.x * 32;
    const int bt = blockIdx.y * 32;
    const int idx = 2 * layer + d;

    const uint32_t* Wd   = Wcat + (size_t)d * dW;
    const float* bd      = bias_l + d * Gsz;
    const float* hprev   = h_in + (size_t)idx * Bsz * Hsz;
    const float* cprev   = c_in + (size_t)idx * Bsz * Hsz;

    const int tid  = threadIdx.x;
    const int warp = tid >> 5, lane = tid & 31;
    const int wm = warp & 1, wn = warp >> 1;
    const int gq = lane >> 2, t4 = lane & 3;
    const int ar = tid >> 3, ac = (tid & 7) * 4;

    const int iters = Kcat / 32;

    float acc[4][4];
    #pragma unroll
    for (int q = 0; q < 4; q++)
        #pragma unroll
        for (int i = 0; i < 4; i++) acc[q][i] = 0.f;

    auto loadA = [&](int k0) -> float4 {
        int b_ = bt + ar;
        if (k0 < Kin) {
            if (inp) return *(const float4*)(inp + (size_t)b_ * Kin + k0 + ac);
            return *(const float4*)(emb + (size_t)tok[(size_t)b_ * tok_stride] * Esz + k0 + ac);
        }
        return *(const float4*)(hprev + (size_t)b_ * Hsz + (k0 - Kin) + ac);
    };
    auto cpW = [&](int k0, int buf) {
        #pragma unroll
        for (int i = 0; i < 4; i++) {
            int g = tid + i * 256;
            int q = g >> 8, r = (g >> 3) & 31, kq = g & 7;
            const uint32_t* src = Wd + (size_t)(q * Hsz + jt + r) * Kcat + k0 + kq * 4;
            cp_async16((uint32_t)__cvta_generic_to_shared(&Ws[buf][q][r][kq * 4]), src);
        }
    };

    float4 a_next = loadA(0);
    cpW(0, 0);
    cp_commit();

    for (int i = 0; i < iters; i++) {
        const int cur = i & 1;
        *(uint4*)&As[cur][ar][ac] = make_uint4(
            f2tf32(a_next.x), f2tf32(a_next.y), f2tf32(a_next.z), f2tf32(a_next.w));
        if (i + 1 < iters) {
            a_next = loadA((i + 1) * 32);
            cpW((i + 1) * 32, 1 - cur);
            cp_commit();
            cp_wait<1>();
        } else {
            cp_wait<0>();
        }
        __syncthreads();
        #pragma unroll
        for (int kc = 0; kc < 32; kc += 8) {
            uint32_t a0 = As[cur][wm * 16 + gq][kc + t4];
            uint32_t a1 = As[cur][wm * 16 + 8 + gq][kc + t4];
            uint32_t a2 = As[cur][wm * 16 + gq][kc + t4 + 4];
            uint32_t a3 = As[cur][wm * 16 + 8 + gq][kc + t4 + 4];
            #pragma unroll
            for (int q = 0; q < 4; q++) {
                uint32_t b0 = Ws[cur][q][wn * 8 + gq][kc + t4];
                uint32_t b1 = Ws[cur][q][wn * 8 + gq][kc + t4 + 4];
                mma_tf32(acc[q], a0, a1, a2, a3, b0, b1);
            }
        }
        __syncthreads();
    }

    // epilogue: torch gate order i,f,g,o
    const int b0r = bt + wm * 16 + gq;
    const int j0  = jt + wn * 8 + t4 * 2;
    #pragma unroll
    for (int rb = 0; rb < 2; rb++)
        #pragma unroll
        for (int rj = 0; rj < 2; rj++) {
            int b_ = b0r + rb * 8;
            int j_ = j0 + rj;
            int ci = rb * 2 + rj;
            float ig = acc[0][ci] + bd[0 * Hsz + j_];
            float fg = acc[1][ci] + bd[1 * Hsz + j_];
            float gg = acc[2][ci] + bd[2 * Hsz + j_];
            float og = acc[3][ci] + bd[3 * Hsz + j_];
            float si = 1.f / (1.f + expf(-ig));
            float sf = 1.f / (1.f + expf(-fg));
            float so = 1.f / (1.f + expf(-og));
            float tg = tanhf(gg);
            float cold = cprev[(size_t)b_ * Hsz + j_];
            float cn = sf * cold + si * tg;
            float hn = so * tanhf(cn);
            c_out[(size_t)idx * Bsz * Hsz + (size_t)b_ * Hsz + j_] = cn;
            h_out[(size_t)idx * Bsz * Hsz + (size_t)b_ * Hsz + j_] = hn;
            lo_out[(size_t)b_ * (2 * Hsz) + d * Hsz + j_] = hn;
        }
}

// ---------------- fused proj: inline 6-way mix + GEMM with W1 ---------------
// out[m*B+b, g] = sum_h (sum_l W2[m,l] hid[l,b,h]) * W1[g,h] + (sum_l W2[m,l]) b1[g] + b2[m]
__global__ __launch_bounds__(256) void proj_fused_mma(
    const float* __restrict__ hid,   // [6, B, H]
    const float* __restrict__ W1,    // [256, 256]
    const float* __restrict__ b1,
    const float* __restrict__ W2,    // [6,6]
    const float* __restrict__ b2,    // [6]
    float* __restrict__ outp)        // [1536, 256]
{
    __shared__ uint32_t As[32][36];
    __shared__ uint32_t Bs[32][36];
    const int gt = blockIdx.x * 32;
    const int rt = blockIdx.y * 32;
    const int m  = rt >> 8;
    const int tid  = threadIdx.x;
    const int warp = tid >> 5, lane = tid & 31;
    const int wm = warp & 1, wn = warp >> 1;
    const int gq = lane >> 2, t4 = lane & 3;
    const int ar = tid >> 3, ac = (tid & 7) * 4;

    float w2r[Dd];
    #pragma unroll
    for (int l = 0; l < Dd; l++) w2r[l] = W2[m * Dd + l];

    float acc[4] = {0.f, 0.f, 0.f, 0.f};
    const int bb = (rt & 255) + ar;

    for (int k0 = 0; k0 < 256; k0 += 32) {
        {
            float sx = 0.f, sy = 0.f, sz = 0.f, sw = 0.f;
            #pragma unroll
            for (int l = 0; l < Dd; l++) {
                float4 v = *(const float4*)(hid + ((size_t)l * Bsz + bb) * Hsz + k0 + ac);
                sx += w2r[l] * v.x; sy += w2r[l] * v.y;
                sz += w2r[l] * v.z; sw += w2r[l] * v.w;
            }
            *(uint4*)&As[ar][ac] = make_uint4(f2tf32(sx), f2tf32(sy), f2tf32(sz), f2tf32(sw));
            float4 vb = *(const float4*)(W1 + (size_t)(gt + ar) * 256 + k0 + ac);
            *(uint4*)&Bs[ar][ac] = make_uint4(f2tf32(vb.x), f2tf32(vb.y), f2tf32(vb.z), f2tf32(vb.w));
        }
        __syncthreads();
        #pragma unroll
        for (int kc = 0; kc < 32; kc += 8) {
            uint32_t a0 = As[wm * 16 + gq][kc + t4];
            uint32_t a1 = As[wm * 16 + 8 + gq][kc + t4];
            uint32_t a2 = As[wm * 16 + gq][kc + t4 + 4];
            uint32_t a3 = As[wm * 16 + 8 + gq][kc + t4 + 4];
            uint32_t b0 = Bs[wn * 8 + gq][kc + t4];
            uint32_t b1r = Bs[wn * 8 + gq][kc + t4 + 4];
            mma_tf32(acc, a0, a1, a2, a3, b0, b1r);
        }
        __syncthreads();
    }

    float sw2 = 0.f;
    #pragma unroll
    for (int l = 0; l < Dd; l++) sw2 += w2r[l];
    const int r0 = rt + wm * 16 + gq;
    const int g0 = gt + wn * 8 + t4 * 2;
    #pragma unroll
    for (int rb = 0; rb < 2; rb++)
        #pragma unroll
        for (int rg = 0; rg < 2; rg++) {
            int row = r0 + rb * 8;
            int g = g0 + rg;
            outp[(size_t)row * 256 + g] = acc[rb * 2 + rg] + sw2 * b1[g] + b2[m];
        }
}

// ---------------- attention ----------------
__global__ void attn_kernel(const float* __restrict__ hcur,
                            const float* __restrict__ eo,
                            float* __restrict__ ctx) {
    int i = blockIdx.x * blockDim.x + threadIdx.x;
    int b = i >> 8, j = i & 255;
    float acc = 0.f;
    #pragma unroll 1
    for (int l = 0; l < Dd; l++) {
        float hv = hcur[((size_t)l * Bsz + b) * Hsz + j];
        float eor[TIN];
        #pragma unroll
        for (int t = 0; t < TIN; t++)
            eor[t] = eo[(((size_t)t * Dd + l) * Bsz + b) * Hsz + j];
        float m = -1e30f;
        #pragma unroll
        for (int t = 0; t < TIN; t++) m = fmaxf(m, hv * eor[t]);
        float s = 0.f, w = 0.f;
        #pragma unroll
        for (int t = 0; t < TIN; t++) {
            float p = expf(hv * eor[t] - m);
            s += p; w += p * eor[t];
        }
        acc += w / s;
    }
    ctx[i] = acc * (1.f / 6.f);
}

// ---------------- attention linear ----------------
__global__ __launch_bounds__(256) void attnlin_kernel(
    const int* __restrict__ tok, int tok_stride,
    const float* __restrict__ dec_emb,
    const float* __restrict__ ctx,
    const float* __restrict__ W,         // [256, 512]
    const float* __restrict__ bvec,
    float* __restrict__ xdec)
{
    __shared__ float As[32][33];
    __shared__ float Bs[32][33];
    const int et = blockIdx.x * 32;
    const int bt = blockIdx.y * 32;
    const int tid = threadIdx.x;
    const int tx = tid & 15, ty = tid >> 4;
    float acc[2][2] = {};

    for (int k0 = 0; k0 < 512; k0 += 32) {
        #pragma unroll
        for (int i = 0; i < 4; i++) {
            int e2 = tid + i * 256;
            int r = e2 >> 5, c = e2 & 31;
            int b_ = bt + r, k = k0 + c;
            float v;
            if (k < 256) v = dec_emb[(size_t)tok[(size_t)b_ * tok_stride] * 256 + k];
            else         v = ctx[(size_t)b_ * 256 + (k - 256)];
            As[r][c] = v;
            Bs[r][c] = W[(size_t)(et + r) * 512 + k];
        }
        __syncthreads();
        #pragma unroll
        for (int kk = 0; kk < 32; kk++) {
            float a0 = As[ty * 2][kk], a1 = As[ty * 2 + 1][kk];
            float w0 = Bs[tx * 2][kk], w1 = Bs[tx * 2 + 1][kk];
            acc[0][0] += a0 * w0; acc[0][1] += a0 * w1;
            acc[1][0] += a1 * w0; acc[1][1] += a1 * w1;
        }
        __syncthreads();
    }
    #pragma unroll
    for (int rr = 0; rr < 2; rr++)
        #pragma unroll
        for (int re = 0; re < 2; re++) {
            int b_ = bt + ty * 2 + rr;
            int e = et + tx * 2 + re;
            xdec[(size_t)b_ * 256 + e] = acc[rr][re] + bvec[e];
        }
}

// ---------------- fc ----------------
__global__ void fc_kernel(const float* __restrict__ top,
                          const float* __restrict__ W,
                          const float* __restrict__ bv,
                          float* __restrict__ outp) {
    int i = blockIdx.x * blockDim.x + threadIdx.x;
    if (i >= Bsz * VDEC) return;
    int b = i / VDEC, v = i % VDEC;
    float s = bv[v];
    const float* tr = top + (size_t)b * 512;
    const float* wr = W + (size_t)v * 512;
    #pragma unroll 8
    for (int k = 0; k < 512; k++) s += tr[k] * wr[k];
    outp[(size_t)b * VDEC + v] = s;
}

// ============================================================================
extern "C" void kernel_launch(void* const* d_in, const int* in_sizes, int n_in,
                              void* d_out, int out_size) {
    const int*   input    = (const int*)  d_in[0];
    const int*   target   = (const int*)  d_in[1];
    const float* enc_emb  = (const float*)d_in[3];
    const float* dec_emb  = (const float*)d_in[4];
    const float* enc_Wih0 = (const float*)d_in[5];
    const float* enc_Wih1 = (const float*)d_in[6];
    const float* enc_Whh  = (const float*)d_in[7];
    const float* enc_b    = (const float*)d_in[8];
    const float* dec_Wih0 = (const float*)d_in[9];
    const float* dec_Wih1 = (const float*)d_in[10];
    const float* dec_Whh  = (const float*)d_in[11];
    const float* dec_b    = (const float*)d_in[12];
    const float* lin_h_W1 = (const float*)d_in[13];
    const float* lin_h_b1 = (const float*)d_in[14];
    const float* lin_h_W2 = (const float*)d_in[15];
    const float* lin_h_b2 = (const float*)d_in[16];
    const float* lin_c_W1 = (const float*)d_in[17];
    const float* lin_c_b1 = (const float*)d_in[18];
    const float* lin_c_W2 = (const float*)d_in[19];
    const float* lin_c_b2 = (const float*)d_in[20];
    const float* lin_a_W1 = (const float*)d_in[21];
    const float* lin_a_b1 = (const float*)d_in[22];
    const float* lin_a_W2 = (const float*)d_in[23];
    const float* lin_a_b2 = (const float*)d_in[24];
    const float* attn_W   = (const float*)d_in[25];
    const float* attn_b   = (const float*)d_in[26];
    const float* fc_W     = (const float*)d_in[27];
    const float* fc_b     = (const float*)d_in[28];
    float* out = (float*)d_out;

    float *enc_out, *h_enc, *c_enc, *h_dec, *c_dec, *ctx, *xdec, *loA, *loB;
    uint32_t* wcat;
    cudaGetSymbolAddress((void**)&enc_out, g_enc_out);
    cudaGetSymbolAddress((void**)&h_enc,   g_h_enc);
    cudaGetSymbolAddress((void**)&c_enc,   g_c_enc);
    cudaGetSymbolAddress((void**)&h_dec,   g_h_dec);
    cudaGetSymbolAddress((void**)&c_dec,   g_c_dec);
    cudaGetSymbolAddress((void**)&ctx,     g_ctx);
    cudaGetSymbolAddress((void**)&xdec,    g_xdec);
    cudaGetSymbolAddress((void**)&loA,     g_loA);
    cudaGetSymbolAddress((void**)&loB,     g_loB);
    cudaGetSymbolAddress((void**)&wcat,    g_wcat);

    const size_t SLAB = (size_t)Dd * Bsz * Hsz;

    {
        long nmax = out_size;
        if ((long)SLAB > nmax) nmax = (long)SLAB;
        init_kernel<<<(int)((nmax + 255) / 256), 256>>>(out, (long)out_size, h_enc, c_enc);
    }
    prep_weights<<<(2 * (WNET / 4) + 255) / 256, 256>>>(
        enc_Wih0, enc_Wih1, enc_Whh, dec_Wih0, dec_Wih1, dec_Whh, wcat);

    // per-net layer offsets (u32 units) and strides
    const long LOFF[3] = {0, 1048576, 2621440};
    const int  KCAT[3] = {512, 768, 768};
    const int  KIN [3] = {256, 512, 512};

    dim3 ggrid(Hsz / 32, Bsz / 32, 2);
    dim3 pgrid(256 / 32, (Dd * Bsz) / 32);
    dim3 agrid(8, 8);

    // ---------------- encoder ----------------
    for (int t = 0; t < TIN; t++) {
        int p = t & 1;
        const float* hI = h_enc + (size_t)p * SLAB;
        const float* cI = c_enc + (size_t)p * SLAB;
        float* hO = h_enc + (size_t)(1 - p) * SLAB;
        float* cO = c_enc + (size_t)(1 - p) * SLAB;

        lstm_gate_mma3<<<ggrid, 256>>>(
            nullptr, input + t, TIN, enc_emb, KIN[0], KCAT[0],
            wcat + LOFF[0], (long)Gsz * KCAT[0],
            enc_b + 0, hI, cI, hO, cO, loA, 0);
        lstm_gate_mma3<<<ggrid, 256>>>(
            loA, nullptr, 0, nullptr, KIN[1], KCAT[1],
            wcat + LOFF[1], (long)Gsz * KCAT[1],
            enc_b + 1 * 2 * Gsz, hI, cI, hO, cO, loB, 1);
        lstm_gate_mma3<<<ggrid, 256>>>(
            loB, nullptr, 0, nullptr, KIN[2], KCAT[2],
            wcat + LOFF[2], (long)Gsz * KCAT[2],
            enc_b + 2 * 2 * Gsz, hI, cI, hO, cO, loA, 2);

        proj_fused_mma<<<pgrid, 256>>>(hO, lin_a_W1, lin_a_b1, lin_a_W2, lin_a_b2,
                                       enc_out + (size_t)t * SLAB);
    }

    const float* hF = h_enc + 0 * SLAB;
    const float* cF = c_enc + 0 * SLAB;

    // ---------------- bridging ----------------
    proj_fused_mma<<<pgrid, 256>>>(hF, lin_h_W1, lin_h_b1, lin_h_W2, lin_h_b2,
                                   h_dec + 0 * SLAB);
    proj_fused_mma<<<pgrid, 256>>>(cF, lin_c_W1, lin_c_b1, lin_c_W2, lin_c_b2,
                                   c_dec + 0 * SLAB);

    // ---------------- decoder (teacher-forced) ----------------
    for (int s = 0; s < TOUT - 1; s++) {
        int p = s & 1;
        const float* hI = h_dec + (size_t)p * SLAB;
        const float* cI = c_dec + (size_t)p * SLAB;
        float* hO = h_dec + (size_t)(1 - p) * SLAB;
        float* cO = c_dec + (size_t)(1 - p) * SLAB;

        attn_kernel<<<(Bsz * Hsz) / 256, 256>>>(hI, enc_out, ctx);
        attnlin_kernel<<<agrid, 256>>>(target + s, TOUT, dec_emb, ctx,
                                       attn_W, attn_b, xdec);

        lstm_gate_mma3<<<ggrid, 256>>>(
            xdec, nullptr, 0, nullptr, KIN[0], KCAT[0],
            wcat + WNET + LOFF[0], (long)Gsz * KCAT[0],
            dec_b + 0, hI, cI, hO, cO, loA, 0);
        lstm_gate_mma3<<<ggrid, 256>>>(
            loA, nullptr, 0, nullptr, KIN[1], KCAT[1],
            wcat + WNET + LOFF[1], (long)Gsz * KCAT[1],
            dec_b + 1 * 2 * Gsz, hI, cI, hO, cO, loB, 1);
        lstm_gate_mma3<<<ggrid, 256>>>(
            loB, nullptr, 0, nullptr, KIN[2], KCAT[2],
            wcat + WNET + LOFF[2], (long)Gsz * KCAT[2],
            dec_b + 2 * 2 * Gsz, hI, cI, hO, cO, loA, 2);

        fc_kernel<<<(Bsz * VDEC + 255) / 256, 256>>>(
            loA, fc_W, fc_b, out + (size_t)(s + 1) * Bsz * VDEC);
    }
}

// round 7
// speedup vs baseline: 1.9786x; 1.0864x over previous
#include <cuda_runtime.h>
#include <math.h>
#include <stdint.h>

// ---------------- problem constants ----------------
#define Bsz   256
#define TIN   32
#define TOUT  29
#define VDEC  72
#define Esz   256
#define Hsz   256
#define Gsz   1024
#define Dd    6
#define Lly   3

#define NSTG  4
#define GATE_ASZ (64 * 36)            // A stage: 64 rows x 36 (padded) u32
#define GATE_WSZ (4 * 32 * 36)        // W stage: 4 gates x 32 rows x 36
#define GATE_SSZ (GATE_ASZ + GATE_WSZ)
#define GATE_SMEM (NSTG * GATE_SSZ * 4)

// ---------------- scratch ----------------
__device__ float g_enc_out[TIN * Dd * Bsz * Hsz];   // ~50MB
__device__ float g_h4[4 * Dd * Bsz * Hsz];          // encoder state, mod-4 slabs
__device__ float g_c4[4 * Dd * Bsz * Hsz];
__device__ float g_h_dec[2 * Dd * Bsz * Hsz];
__device__ float g_c_dec[2 * Dd * Bsz * Hsz];
__device__ float g_ctx[Bsz * Hsz];
__device__ float g_xdec[Bsz * Esz];
__device__ float g_lo0[2 * Bsz * 2 * Hsz];  // enc layer0 out, t-parity buffered
__device__ float g_lo1[2 * Bsz * 2 * Hsz];  // enc layer1 out
__device__ float g_loA[Bsz * 2 * Hsz];      // dec layer0 out
__device__ float g_loB[Bsz * 2 * Hsz];      // dec layer1 out
__device__ float g_loC[Bsz * 2 * Hsz];      // dec layer2 out
#define WNET 4194304
__device__ uint32_t g_wcat[2 * WNET];       // tf32 weights, 32MB

// ---------------- helpers ----------------
__device__ __forceinline__ uint32_t f2tf32(float f) {
    uint32_t r;
    asm("cvt.rna.tf32.f32 %0, %1;" : "=r"(r) : "f"(f));
    return r;
}
__device__ __forceinline__ void mma_tf32(float* c,
    uint32_t a0, uint32_t a1, uint32_t a2, uint32_t a3,
    uint32_t b0, uint32_t b1) {
    asm volatile(
        "mma.sync.aligned.m16n8k8.row.col.f32.tf32.tf32.f32 "
        "{%0,%1,%2,%3}, {%4,%5,%6,%7}, {%8,%9}, {%0,%1,%2,%3};"
        : "+f"(c[0]), "+f"(c[1]), "+f"(c[2]), "+f"(c[3])
        : "r"(a0), "r"(a1), "r"(a2), "r"(a3), "r"(b0), "r"(b1));
}
__device__ __forceinline__ void cp_async16(uint32_t dst_smem, const void* src) {
    asm volatile("cp.async.ca.shared.global [%0], [%1], 16;" :: "r"(dst_smem), "l"(src));
}
__device__ __forceinline__ void cp_commit() { asm volatile("cp.async.commit_group;"); }
template<int N> __device__ __forceinline__ void cp_wait() {
    asm volatile("cp.async.wait_group %0;" :: "n"(N));
}

// ---------------- init ----------------
__global__ void init_kernel(float* __restrict__ out, long nout,
                            float* __restrict__ h3, float* __restrict__ c3) {
    long i = (long)blockIdx.x * blockDim.x + threadIdx.x;
    if (i < (long)Dd * Bsz * Hsz) { h3[i] = 0.f; c3[i] = 0.f; }
    if (i < nout) {
        float v = 0.f;
        if (i < (long)Bsz * VDEC && (i % VDEC) == 1) v = 1.f;
        out[i] = v;
    }
}

// ---------------- weight prep: fp32 -> tf32, [Wih|Whh] concat layout --------
__global__ void prep_weights(const float* __restrict__ eW0, const float* __restrict__ eW1,
                             const float* __restrict__ eWhh,
                             const float* __restrict__ dW0, const float* __restrict__ dW1,
                             const float* __restrict__ dWhh,
                             uint32_t* __restrict__ wcat) {
    long idx = (long)blockIdx.x * blockDim.x + threadIdx.x;   // 4-elem units
    if (idx >= 2 * (WNET / 4)) return;
    int n = (int)(idx >= (WNET / 4));
    long r0 = idx - (long)n * (WNET / 4);
    int l, Kcat4, Kin; long base4;
    if (r0 < 262144)        { l = 0; base4 = 0;      Kcat4 = 128; Kin = 256; }
    else if (r0 < 655360)   { l = 1; base4 = 262144; Kcat4 = 192; Kin = 512; }
    else                    { l = 2; base4 = 655360; Kcat4 = 192; Kin = 512; }
    long r1 = r0 - base4;
    int d  = (int)(r1 / (1024L * Kcat4));
    int rr = (int)((r1 / Kcat4) & 1023);
    int k  = (int)(r1 % Kcat4) * 4;

    const float* W0  = n ? dW0  : eW0;
    const float* W1  = n ? dW1  : eW1;
    const float* Whh = n ? dWhh : eWhh;
    float4 v;
    if (k < Kin) {
        if (l == 0) v = *(const float4*)(W0 + ((size_t)d * 1024 + rr) * 256 + k);
        else        v = *(const float4*)(W1 + (((size_t)(l - 1) * 2 + d) * 1024 + rr) * 512 + k);
    } else {
        v = *(const float4*)(Whh + (((size_t)l * 2 + d) * 1024 + rr) * 256 + (k - Kin));
    }
    uint4 o = make_uint4(f2tf32(v.x), f2tf32(v.y), f2tf32(v.z), f2tf32(v.w));
    *(uint4*)(wcat + idx * 4) = o;
}

// ---------------- gate block: 64b x 32j x 4 gates, 4-stage cp.async pipe ----
// hprev/cprev/hw/cw already offset to the [B,H] slice for this (layer,dir).
__device__ __forceinline__ void gate_block(
    const float* inp, const int* tok, int tok_stride, const float* emb,
    int Kin, int Kcat, const uint32_t* Wd, const float* bd,
    const float* hprev, const float* cprev, float* hw, float* cw,
    float* lo_out, int d, int jt, int bt, uint32_t* sm)
{
    const int tid = threadIdx.x, warp = tid >> 5, lane = tid & 31;
    const int wm = warp & 3, wj = warp >> 2;
    const int gq = lane >> 2, t4 = lane & 3;
    const int ar = tid >> 3, ac4 = (tid & 7) * 4;

    const float* aRow0;
    const float* aRow1;
    if (inp) {
        aRow0 = inp + (size_t)(bt + ar) * Kin;
        aRow1 = inp + (size_t)(bt + ar + 32) * Kin;
    } else {
        aRow0 = emb + (size_t)tok[(size_t)(bt + ar) * tok_stride] * Esz;
        aRow1 = emb + (size_t)tok[(size_t)(bt + ar + 32) * tok_stride] * Esz;
    }
    const float* hRow0 = hprev + (size_t)(bt + ar) * Hsz;
    const float* hRow1 = hprev + (size_t)(bt + ar + 32) * Hsz;

    const int iters = Kcat / 32;

    auto stage = [&](int i) {
        int stg = i & (NSTG - 1);
        uint32_t base = (uint32_t)__cvta_generic_to_shared(sm + stg * GATE_SSZ);
        int k = i * 32 + ac4;
        const float* s0 = (k < Kin) ? (aRow0 + k) : (hRow0 + (k - Kin));
        const float* s1 = (k < Kin) ? (aRow1 + k) : (hRow1 + (k - Kin));
        cp_async16(base + (ar * 36 + ac4) * 4, s0);
        cp_async16(base + ((ar + 32) * 36 + ac4) * 4, s1);
        uint32_t wb = base + GATE_ASZ * 4;
        #pragma unroll
        for (int r4 = 0; r4 < 4; r4++) {
            int g = tid + r4 * 256;
            int q = g >> 8, r = (g >> 3) & 31, kq = (g & 7) * 4;
            const uint32_t* src = Wd + (size_t)(q * Hsz + jt + r) * Kcat + i * 32 + kq;
            cp_async16(wb + ((q * 32 + r) * 36 + kq) * 4, src);
        }
    };

    float acc[4][2][4];
    #pragma unroll
    for (int q = 0; q < 4; q++)
        #pragma unroll
        for (int jf = 0; jf < 2; jf++)
            #pragma unroll
            for (int i = 0; i < 4; i++) acc[q][jf][i] = 0.f;

    stage(0); cp_commit();
    stage(1); cp_commit();

    for (int i = 0; i < iters; i++) {
        if (i + 2 < iters) stage(i + 2);
        cp_commit();
        cp_wait<2>();
        __syncthreads();
        const uint32_t* Ab = sm + (i & (NSTG - 1)) * GATE_SSZ;
        const uint32_t* Wb = Ab + GATE_ASZ;
        #pragma unroll
        for (int kc = 0; kc < 32; kc += 8) {
            uint32_t a0 = Ab[(wm * 16 + gq) * 36 + kc + t4];
            uint32_t a1 = Ab[(wm * 16 + 8 + gq) * 36 + kc + t4];
            uint32_t a2 = Ab[(wm * 16 + gq) * 36 + kc + t4 + 4];
            uint32_t a3 = Ab[(wm * 16 + 8 + gq) * 36 + kc + t4 + 4];
            #pragma unroll
            for (int q = 0; q < 4; q++)
                #pragma unroll
                for (int jf = 0; jf < 2; jf++) {
                    int row = q * 32 + wj * 16 + jf * 8 + gq;
                    uint32_t b0 = Wb[row * 36 + kc + t4];
                    uint32_t b1 = Wb[row * 36 + kc + t4 + 4];
                    mma_tf32(acc[q][jf], a0, a1, a2, a3, b0, b1);
                }
        }
        // single barrier per iter: 4-stage ring, write (i+2)%4 vs reads i%4 /
        // (i-1)%4 -> distances 2,3 mod 4, never 0.
    }

    // epilogue: torch gate order i,f,g,o
    const int b0r = bt + wm * 16 + gq;
    const int jb  = jt + wj * 16;
    #pragma unroll
    for (int jf = 0; jf < 2; jf++)
        #pragma unroll
        for (int rb = 0; rb < 2; rb++)
            #pragma unroll
            for (int rj = 0; rj < 2; rj++) {
                int b_ = b0r + rb * 8;
                int j_ = jb + jf * 8 + t4 * 2 + rj;
                int ci = rb * 2 + rj;
                float ig = acc[0][jf][ci] + bd[0 * Hsz + j_];
                float fg = acc[1][jf][ci] + bd[1 * Hsz + j_];
                float gg = acc[2][jf][ci] + bd[2 * Hsz + j_];
                float og = acc[3][jf][ci] + bd[3 * Hsz + j_];
                float si = 1.f / (1.f + expf(-ig));
                float sf = 1.f / (1.f + expf(-fg));
                float so = 1.f / (1.f + expf(-og));
                float tg = tanhf(gg);
                float cold = cprev[(size_t)b_ * Hsz + j_];
                float cn = sf * cold + si * tg;
                float hn = so * tanhf(cn);
                cw[(size_t)b_ * Hsz + j_] = cn;
                hw[(size_t)b_ * Hsz + j_] = hn;
                if (lo_out)
                    lo_out[(size_t)b_ * (2 * Hsz) + d * Hsz + j_] = hn;
            }
}

// ---------------- proj block: 32r x 32g tile of the fused mix+GEMM ----------
__device__ __forceinline__ void proj_block(
    const float* hid, const float* W1, const float* b1,
    const float* W2, const float* b2, float* outp,
    int gt, int rt, uint32_t* smbuf)
{
    uint32_t* As = smbuf;             // [32][36]
    uint32_t* Bs = smbuf + 32 * 36;   // [32][36]
    const int m  = rt >> 8;
    const int tid  = threadIdx.x;
    const int warp = tid >> 5, lane = tid & 31;
    const int wm = warp & 1, wn = warp >> 1;
    const int gq = lane >> 2, t4 = lane & 3;
    const int ar = tid >> 3, ac = (tid & 7) * 4;

    float w2r[Dd];
    #pragma unroll
    for (int l = 0; l < Dd; l++) w2r[l] = W2[m * Dd + l];

    float acc[4] = {0.f, 0.f, 0.f, 0.f};
    const int bb = (rt & 255) + ar;

    for (int k0 = 0; k0 < 256; k0 += 32) {
        {
            float sx = 0.f, sy = 0.f, sz = 0.f, sw = 0.f;
            #pragma unroll
            for (int l = 0; l < Dd; l++) {
                float4 v = *(const float4*)(hid + ((size_t)l * Bsz + bb) * Hsz + k0 + ac);
                sx += w2r[l] * v.x; sy += w2r[l] * v.y;
                sz += w2r[l] * v.z; sw += w2r[l] * v.w;
            }
            *(uint4*)&As[ar * 36 + ac] = make_uint4(f2tf32(sx), f2tf32(sy), f2tf32(sz), f2tf32(sw));
            float4 vb = *(const float4*)(W1 + (size_t)(gt + ar) * 256 + k0 + ac);
            *(uint4*)&Bs[ar * 36 + ac] = make_uint4(f2tf32(vb.x), f2tf32(vb.y), f2tf32(vb.z), f2tf32(vb.w));
        }
        __syncthreads();
        #pragma unroll
        for (int kc = 0; kc < 32; kc += 8) {
            uint32_t a0 = As[(wm * 16 + gq) * 36 + kc + t4];
            uint32_t a1 = As[(wm * 16 + 8 + gq) * 36 + kc + t4];
            uint32_t a2 = As[(wm * 16 + gq) * 36 + kc + t4 + 4];
            uint32_t a3 = As[(wm * 16 + 8 + gq) * 36 + kc + t4 + 4];
            uint32_t b0 = Bs[(wn * 8 + gq) * 36 + kc + t4];
            uint32_t b1r = Bs[(wn * 8 + gq) * 36 + kc + t4 + 4];
            mma_tf32(acc, a0, a1, a2, a3, b0, b1r);
        }
        __syncthreads();
    }

    float sw2 = 0.f;
    #pragma unroll
    for (int l = 0; l < Dd; l++) sw2 += w2r[l];
    const int r0 = rt + wm * 16 + gq;
    const int g0 = gt + wn * 8 + t4 * 2;
    #pragma unroll
    for (int rb = 0; rb < 2; rb++)
        #pragma unroll
        for (int rg = 0; rg < 2; rg++) {
            int row = r0 + rb * 8;
            int g = g0 + rg;
            outp[(size_t)row * 256 + g] = acc[rb * 2 + rg] + sw2 * b1[g] + b2[m];
        }
}

// ---------------- encoder wavefront kernel ----------------------------------
// One launch = wavefront w: layer0(t=w), layer1(t=w-1), layer2(t=w-2) and
// proj(t=w-3), all as independent blocks (disjoint mod-4 state slabs).
__global__ __launch_bounds__(256) void enc_wave(
    int w,
    const int* __restrict__ input, const float* __restrict__ emb,
    const uint32_t* __restrict__ wcat, const float* __restrict__ enc_b,
    float* __restrict__ lo0, float* __restrict__ lo1,
    float* __restrict__ h4, float* __restrict__ c4,
    float* __restrict__ enc_out,
    const float* __restrict__ aW1, const float* __restrict__ ab1,
    const float* __restrict__ aW2, const float* __restrict__ ab2)
{
    extern __shared__ uint32_t sm[];
    const size_t SLAB = (size_t)Dd * Bsz * Hsz;
    const size_t B2H  = (size_t)Bsz * 2 * Hsz;
    const int bi = blockIdx.x;

    if (bi < 192) {
        const int l = bi / 64, r = bi % 64;
        const int t = w - l;
        if (t < 0 || t >= TIN) return;
        const int jt = (r & 7) * 32;
        const int bt = ((r >> 3) & 3) * 64;
        const int d  = r >> 5;
        const int idx = 2 * l + d;

        const float* hprev = h4 + (size_t)((t + 3) & 3) * SLAB + (size_t)idx * Bsz * Hsz;
        const float* cprev = c4 + (size_t)((t + 3) & 3) * SLAB + (size_t)idx * Bsz * Hsz;
        float* hw = h4 + (size_t)(t & 3) * SLAB + (size_t)idx * Bsz * Hsz;
        float* cw = c4 + (size_t)(t & 3) * SLAB + (size_t)idx * Bsz * Hsz;

        const float* inp = nullptr;
        const int* tok = nullptr;
        int Kin, Kcat;
        const uint32_t* Wd;
        const float* bd;
        float* lo;
        if (l == 0) {
            tok = input + t; Kin = 256; Kcat = 512;
            Wd = wcat + (size_t)d * Gsz * 512;
            bd = enc_b + d * Gsz;
            lo = lo0 + (size_t)(t & 1) * B2H;
        } else if (l == 1) {
            inp = lo0 + (size_t)(t & 1) * B2H; Kin = 512; Kcat = 768;
            Wd = wcat + 1048576 + (size_t)d * Gsz * 768;
            bd = enc_b + (2 + d) * Gsz;
            lo = lo1 + (size_t)(t & 1) * B2H;
        } else {
            inp = lo1 + (size_t)(t & 1) * B2H; Kin = 512; Kcat = 768;
            Wd = wcat + 2621440 + (size_t)d * Gsz * 768;
            bd = enc_b + (4 + d) * Gsz;
            lo = nullptr;
        }
        gate_block(inp, tok, TIN, emb, Kin, Kcat, Wd, bd,
                   hprev, cprev, hw, cw, lo, d, jt, bt, sm);
    } else {
        const int t = w - 3;
        if (t < 0) return;
        const int pr = bi - 192;           // 0..383
        const int gt = (pr & 7) * 32;
        const int rt = (pr >> 3) * 32;
        const float* hid = h4 + (size_t)(t & 3) * SLAB;
        proj_block(hid, aW1, ab1, aW2, ab2,
                   enc_out + (size_t)t * SLAB, gt, rt, sm);
    }
}

// ---------------- decoder gate kernel (same block, 2-parity state) ----------
__global__ __launch_bounds__(256) void lstm_gate_v4(
    const float* __restrict__ inp, int Kin, int Kcat,
    const uint32_t* __restrict__ Wcat, long dW,
    const float* __restrict__ bias_l,
    const float* __restrict__ h_in, const float* __restrict__ c_in,
    float* __restrict__ h_out, float* __restrict__ c_out,
    float* __restrict__ lo_out, int layer)
{
    extern __shared__ uint32_t sm[];
    const int d  = blockIdx.z;
    const int jt = blockIdx.x * 32;
    const int bt = blockIdx.y * 64;
    const int idx = 2 * layer + d;
    gate_block(inp, nullptr, 0, nullptr, Kin, Kcat,
               Wcat + (size_t)d * dW, bias_l + d * Gsz,
               h_in + (size_t)idx * Bsz * Hsz, c_in + (size_t)idx * Bsz * Hsz,
               h_out + (size_t)idx * Bsz * Hsz, c_out + (size_t)idx * Bsz * Hsz,
               lo_out, d, jt, bt, sm);
}

// ---------------- standalone proj (bridging) --------------------------------
__global__ __launch_bounds__(256) void proj_fused_mma(
    const float* __restrict__ hid, const float* __restrict__ W1,
    const float* __restrict__ b1, const float* __restrict__ W2,
    const float* __restrict__ b2, float* __restrict__ outp)
{
    __shared__ uint32_t smbuf[2 * 32 * 36];
    proj_block(hid, W1, b1, W2, b2, outp,
               blockIdx.x * 32, blockIdx.y * 32, smbuf);
}

// ---------------- attention ----------------
__global__ void attn_kernel(const float* __restrict__ hcur,
                            const float* __restrict__ eo,
                            float* __restrict__ ctx) {
    int i = blockIdx.x * blockDim.x + threadIdx.x;
    int b = i >> 8, j = i & 255;
    float acc = 0.f;
    #pragma unroll 1
    for (int l = 0; l < Dd; l++) {
        float hv = hcur[((size_t)l * Bsz + b) * Hsz + j];
        float eor[TIN];
        #pragma unroll
        for (int t = 0; t < TIN; t++)
            eor[t] = eo[(((size_t)t * Dd + l) * Bsz + b) * Hsz + j];
        float m = -1e30f;
        #pragma unroll
        for (int t = 0; t < TIN; t++) m = fmaxf(m, hv * eor[t]);
        float s = 0.f, w = 0.f;
        #pragma unroll
        for (int t = 0; t < TIN; t++) {
            float p = expf(hv * eor[t] - m);
            s += p; w += p * eor[t];
        }
        acc += w / s;
    }
    ctx[i] = acc * (1.f / 6.f);
}

// ---------------- attention linear ----------------
__global__ __launch_bounds__(256) void attnlin_kernel(
    const int* __restrict__ tok, int tok_stride,
    const float* __restrict__ dec_emb,
    const float* __restrict__ ctx,
    const float* __restrict__ W,         // [256, 512]
    const float* __restrict__ bvec,
    float* __restrict__ xdec)
{
    __shared__ float As[32][33];
    __shared__ float Bs[32][33];
    const int et = blockIdx.x * 32;
    const int bt = blockIdx.y * 32;
    const int tid = threadIdx.x;
    const int tx = tid & 15, ty = tid >> 4;
    float acc[2][2] = {};

    for (int k0 = 0; k0 < 512; k0 += 32) {
        #pragma unroll
        for (int i = 0; i < 4; i++) {
            int e2 = tid + i * 256;
            int r = e2 >> 5, c = e2 & 31;
            int b_ = bt + r, k = k0 + c;
            float v;
            if (k < 256) v = dec_emb[(size_t)tok[(size_t)b_ * tok_stride] * 256 + k];
            else         v = ctx[(size_t)b_ * 256 + (k - 256)];
            As[r][c] = v;
            Bs[r][c] = W[(size_t)(et + r) * 512 + k];
        }
        __syncthreads();
        #pragma unroll
        for (int kk = 0; kk < 32; kk++) {
            float a0 = As[ty * 2][kk], a1 = As[ty * 2 + 1][kk];
            float w0 = Bs[tx * 2][kk], w1 = Bs[tx * 2 + 1][kk];
            acc[0][0] += a0 * w0; acc[0][1] += a0 * w1;
            acc[1][0] += a1 * w0; acc[1][1] += a1 * w1;
        }
        __syncthreads();
    }
    #pragma unroll
    for (int rr = 0; rr < 2; rr++)
        #pragma unroll
        for (int re = 0; re < 2; re++) {
            int b_ = bt + ty * 2 + rr;
            int e = et + tx * 2 + re;
            xdec[(size_t)b_ * 256 + e] = acc[rr][re] + bvec[e];
        }
}

// ---------------- fc ----------------
__global__ void fc_kernel(const float* __restrict__ top,
                          const float* __restrict__ W,
                          const float* __restrict__ bv,
                          float* __restrict__ outp) {
    int i = blockIdx.x * blockDim.x + threadIdx.x;
    if (i >= Bsz * VDEC) return;
    int b = i / VDEC, v = i % VDEC;
    float s = bv[v];
    const float* tr = top + (size_t)b * 512;
    const float* wr = W + (size_t)v * 512;
    #pragma unroll 8
    for (int k = 0; k < 512; k++) s += tr[k] * wr[k];
    outp[(size_t)b * VDEC + v] = s;
}

// ============================================================================
extern "C" void kernel_launch(void* const* d_in, const int* in_sizes, int n_in,
                              void* d_out, int out_size) {
    const int*   input    = (const int*)  d_in[0];
    const int*   target   = (const int*)  d_in[1];
    const float* enc_emb  = (const float*)d_in[3];
    const float* dec_emb  = (const float*)d_in[4];
    const float* enc_Wih0 = (const float*)d_in[5];
    const float* enc_Wih1 = (const float*)d_in[6];
    const float* enc_Whh  = (const float*)d_in[7];
    const float* enc_b    = (const float*)d_in[8];
    const float* dec_Wih0 = (const float*)d_in[9];
    const float* dec_Wih1 = (const float*)d_in[10];
    const float* dec_Whh  = (const float*)d_in[11];
    const float* dec_b    = (const float*)d_in[12];
    const float* lin_h_W1 = (const float*)d_in[13];
    const float* lin_h_b1 = (const float*)d_in[14];
    const float* lin_h_W2 = (const float*)d_in[15];
    const float* lin_h_b2 = (const float*)d_in[16];
    const float* lin_c_W1 = (const float*)d_in[17];
    const float* lin_c_b1 = (const float*)d_in[18];
    const float* lin_c_W2 = (const float*)d_in[19];
    const float* lin_c_b2 = (const float*)d_in[20];
    const float* lin_a_W1 = (const float*)d_in[21];
    const float* lin_a_b1 = (const float*)d_in[22];
    const float* lin_a_W2 = (const float*)d_in[23];
    const float* lin_a_b2 = (const float*)d_in[24];
    const float* attn_W   = (const float*)d_in[25];
    const float* attn_b   = (const float*)d_in[26];
    const float* fc_W     = (const float*)d_in[27];
    const float* fc_b     = (const float*)d_in[28];
    float* out = (float*)d_out;

    float *enc_out, *h4, *c4, *h_dec, *c_dec, *ctx, *xdec;
    float *lo0, *lo1, *loA, *loB, *loC;
    uint32_t* wcat;
    cudaGetSymbolAddress((void**)&enc_out, g_enc_out);
    cudaGetSymbolAddress((void**)&h4,      g_h4);
    cudaGetSymbolAddress((void**)&c4,      g_c4);
    cudaGetSymbolAddress((void**)&h_dec,   g_h_dec);
    cudaGetSymbolAddress((void**)&c_dec,   g_c_dec);
    cudaGetSymbolAddress((void**)&ctx,     g_ctx);
    cudaGetSymbolAddress((void**)&xdec,    g_xdec);
    cudaGetSymbolAddress((void**)&lo0,     g_lo0);
    cudaGetSymbolAddress((void**)&lo1,     g_lo1);
    cudaGetSymbolAddress((void**)&loA,     g_loA);
    cudaGetSymbolAddress((void**)&loB,     g_loB);
    cudaGetSymbolAddress((void**)&loC,     g_loC);
    cudaGetSymbolAddress((void**)&wcat,    g_wcat);

    cudaFuncSetAttribute(enc_wave,
                         cudaFuncAttributeMaxDynamicSharedMemorySize, GATE_SMEM);
    cudaFuncSetAttribute(lstm_gate_v4,
                         cudaFuncAttributeMaxDynamicSharedMemorySize, GATE_SMEM);

    const size_t SLAB = (size_t)Dd * Bsz * Hsz;

    {
        long nmax = out_size;
        if ((long)SLAB > nmax) nmax = (long)SLAB;
        init_kernel<<<(int)((nmax + 255) / 256), 256>>>(
            out, (long)out_size, h4 + 3 * SLAB, c4 + 3 * SLAB);
    }
    prep_weights<<<(2 * (WNET / 4) + 255) / 256, 256>>>(
        enc_Wih0, enc_Wih1, enc_Whh, dec_Wih0, dec_Wih1, dec_Whh, wcat);

    const long LOFF[3] = {0, 1048576, 2621440};
    const int  KCAT[3] = {512, 768, 768};
    const int  KIN [3] = {256, 512, 512};

    // ---------------- encoder: intra-launch wavefront ----------------
    for (int w = 0; w < TIN + 3; w++) {
        enc_wave<<<576, 256, GATE_SMEM>>>(
            w, input, enc_emb, wcat, enc_b, lo0, lo1, h4, c4,
            enc_out, lin_a_W1, lin_a_b1, lin_a_W2, lin_a_b2);
    }

    const float* hF = h4 + 3 * SLAB;   // step 31 -> slab 31&3 = 3
    const float* cF = c4 + 3 * SLAB;

    // ---------------- bridging ----------------
    dim3 pgrid(256 / 32, (Dd * Bsz) / 32);
    proj_fused_mma<<<pgrid, 256>>>(hF, lin_h_W1, lin_h_b1, lin_h_W2, lin_h_b2,
                                   h_dec + 0 * SLAB);
    proj_fused_mma<<<pgrid, 256>>>(cF, lin_c_W1, lin_c_b1, lin_c_W2, lin_c_b2,
                                   c_dec + 0 * SLAB);

    // ---------------- decoder (teacher-forced, serial) ----------------
    dim3 ggrid(Hsz / 32, Bsz / 64, 2);   // 64 blocks
    dim3 agrid(8, 8);
    for (int s = 0; s < TOUT - 1; s++) {
        int p = s & 1;
        const float* hI = h_dec + (size_t)p * SLAB;
        const float* cI = c_dec + (size_t)p * SLAB;
        float* hO = h_dec + (size_t)(1 - p) * SLAB;
        float* cO = c_dec + (size_t)(1 - p) * SLAB;

        attn_kernel<<<(Bsz * Hsz) / 256, 256>>>(hI, enc_out, ctx);
        attnlin_kernel<<<agrid, 256>>>(target + s, TOUT, dec_emb, ctx,
                                       attn_W, attn_b, xdec);

        lstm_gate_v4<<<ggrid, 256, GATE_SMEM>>>(
            xdec, KIN[0], KCAT[0], wcat + WNET + LOFF[0], (long)Gsz * KCAT[0],
            dec_b, hI, cI, hO, cO, loA, 0);
        lstm_gate_v4<<<ggrid, 256, GATE_SMEM>>>(
            loA, KIN[1], KCAT[1], wcat + WNET + LOFF[1], (long)Gsz * KCAT[1],
            dec_b + 1 * 2 * Gsz, hI, cI, hO, cO, loB, 1);
        lstm_gate_v4<<<ggrid, 256, GATE_SMEM>>>(
            loB, KIN[2], KCAT[2], wcat + WNET + LOFF[2], (long)Gsz * KCAT[2],
            dec_b + 2 * 2 * Gsz, hI, cI, hO, cO, loC, 2);

        fc_kernel<<<(Bsz * VDEC + 255) / 256, 256>>>(
            loC, fc_W, fc_b, out + (size_t)(s + 1) * Bsz * VDEC);
    }
}